// round 8
// baseline (speedup 1.0000x reference)
#include <cuda_runtime.h>
#include <math.h>
#include <stdint.h>

#define B_    8
#define N_    1024
#define DIM_  768
#define H_    8
#define HD_   96
#define E_    24
#define NT    (B_*N_)      /* 8192 tokens */
#define NA    (NT*H_)      /* 65536 assignments */
#define SCALE_ 0.10206207261596575f  /* 96^-0.5 */

/* ------------------------- scratch (device globals) ------------------------- */
__device__ float g_gate[NA];
__device__ float g_me[E_];
__device__ float g_z;
__device__ int   g_ecount[E_];
__device__ int   g_elist[E_*NA];
__device__ float g_k[NT*HD_];
__device__ float g_v[NT*HD_];
__device__ float g_q[(size_t)NA*HD_];
__device__ float g_o[(size_t)NA*HD_];
__device__ float g_contrib[(size_t)NA*DIM_];   /* 201 MB: per-assignment reduce rows */

__device__ __forceinline__ uint32_t f2tf32(float f) {
    uint32_t r;
    asm("cvt.rna.tf32.f32 %0, %1;" : "=r"(r) : "f"(f));
    return r;
}

__device__ __forceinline__ void mma_tf32(float* d, const uint32_t* a, const uint32_t* b) {
    asm("mma.sync.aligned.m16n8k8.row.col.f32.tf32.tf32.f32 "
        "{%0,%1,%2,%3}, {%4,%5,%6,%7}, {%8,%9}, {%0,%1,%2,%3};"
        : "+f"(d[0]), "+f"(d[1]), "+f"(d[2]), "+f"(d[3])
        : "r"(a[0]), "r"(a[1]), "r"(a[2]), "r"(a[3]), "r"(b[0]), "r"(b[1]));
}

/* ------------------------------- zero counters ------------------------------ */
__global__ void zero_kernel() {
    int i = threadIdx.x;
    if (i < E_) { g_me[i] = 0.f; g_ecount[i] = 0; }
    if (i == 0) g_z = 0.f;
}

/* --------------------- gating: logits, softmax, top-8, lists (fp32) --------- */
__global__ void gate_kernel(const float* __restrict__ x,
                            const float* __restrict__ Wg,
                            const int*   __restrict__ task_p) {
    __shared__ float sme[E_];
    __shared__ float sz;
    __shared__ int   scnt[E_];
    __shared__ int   sbase[E_];
    int tid  = threadIdx.x;
    int warp = tid >> 5;
    int lane = tid & 31;
    int t = blockIdx.x * 8 + warp;

    if (tid < E_) { sme[tid] = 0.f; scnt[tid] = 0; }
    if (tid == 0) sz = 0.f;
    __syncthreads();

    int task = *task_p;
    const float* wg = Wg + (size_t)task * DIM_ * E_;
    const float* xr = x + (size_t)t * DIM_;

    float acc = 0.f;
    if (lane < E_) {
        #pragma unroll 4
        for (int d = 0; d < DIM_; d++) acc += xr[d] * wg[d * E_ + lane];
    }
    float logit = (lane < E_) ? acc : -1e30f;

    float m = logit;
    #pragma unroll
    for (int o = 16; o >= 1; o >>= 1) m = fmaxf(m, __shfl_xor_sync(0xffffffffu, m, o));
    float p = (lane < E_) ? expf(logit - m) : 0.f;
    float s = p;
    #pragma unroll
    for (int o = 16; o >= 1; o >>= 1) s += __shfl_xor_sync(0xffffffffu, s, o);
    float prob = p / s;
    float lse = m + logf(s);
    if (lane == 0) atomicAdd(&sz, lse * lse);
    if (lane < E_) atomicAdd(&sme[lane], prob);

    float val = (lane < E_) ? prob : -1.f;
    float sel_g = 0.f; int sel_e = 0;
    #pragma unroll
    for (int it = 0; it < H_; it++) {
        float mm = val;
        #pragma unroll
        for (int o = 16; o >= 1; o >>= 1) mm = fmaxf(mm, __shfl_xor_sync(0xffffffffu, mm, o));
        unsigned msk = __ballot_sync(0xffffffffu, val == mm);
        int src = __ffs(msk) - 1;
        if (lane == src) val = -1.f;
        if (lane == it) { sel_e = src; sel_g = mm; }
    }
    float gv = (lane < H_) ? sel_g : 0.f;
    #pragma unroll
    for (int o = 16; o >= 1; o >>= 1) gv += __shfl_xor_sync(0xffffffffu, gv, o);
    float denom = gv + 1e-6f;

    int pos = 0;
    if (lane < H_) pos = atomicAdd(&scnt[sel_e], 1);
    __syncthreads();
    if (tid < E_) sbase[tid] = atomicAdd(&g_ecount[tid], scnt[tid]);
    __syncthreads();
    if (lane < H_) {
        int a = t * H_ + lane;
        g_gate[a] = sel_g / denom;
        g_elist[sel_e * NA + sbase[sel_e] + pos] = a;
    }
    if (tid < E_) atomicAdd(&g_me[tid], sme[tid]);
    if (tid == 0) atomicAdd(&g_z, sz);
}

/* ----------------- kv projection (R2 SIMT, measured 98.7us) ----------------- */
__global__ void kv_kernel(const float* __restrict__ x,
                          const float* __restrict__ Wkv,
                          const float* __restrict__ bkv) {
    __shared__ float xsT[32][68];
    __shared__ float ws[32][68];
    int r0 = blockIdx.x * 64;
    int c0 = blockIdx.y * 64;
    int tid = threadIdx.x;
    int ty = tid >> 4, tx = tid & 15;
    float acc[4][4] = {};

    for (int k0 = 0; k0 < DIM_; k0 += 32) {
        for (int i = tid; i < 64 * 32; i += 256) {
            int r = i >> 5, k = i & 31;
            xsT[k][r] = x[(size_t)(r0 + r) * DIM_ + k0 + k];
        }
        for (int i = tid; i < 32 * 64; i += 256) {
            int k = i >> 6, c = i & 63;
            ws[k][c] = Wkv[(size_t)(k0 + k) * (2 * HD_) + c0 + c];
        }
        __syncthreads();
        #pragma unroll
        for (int k = 0; k < 32; k++) {
            float4 a4 = *(const float4*)&xsT[k][ty * 4];
            float4 b4 = *(const float4*)&ws[k][tx * 4];
            float av[4] = {a4.x, a4.y, a4.z, a4.w};
            float bv[4] = {b4.x, b4.y, b4.z, b4.w};
            #pragma unroll
            for (int i = 0; i < 4; i++)
                #pragma unroll
                for (int j = 0; j < 4; j++) acc[i][j] += av[i] * bv[j];
        }
        __syncthreads();
    }
    #pragma unroll
    for (int i = 0; i < 4; i++) {
        int r = r0 + ty * 4 + i;
        #pragma unroll
        for (int j = 0; j < 4; j++) {
            int c = c0 + tx * 4 + j;
            float v = acc[i][j] + bkv[c];
            if (c < HD_) g_k[(size_t)r * HD_ + c]          = v;
            else         g_v[(size_t)r * HD_ + (c - HD_)]  = v;
        }
    }
}

/* ---------- grouped q projection, tf32 mma: gathered x @ W1[e] -------------- */
#define Q_SMEM_WORDS (128*68 + 96*68)
__global__ void __launch_bounds__(256) q_tc_kernel(const float* __restrict__ x,
                                                   const float* __restrict__ W1) {
    int e = blockIdx.y;
    int count = g_ecount[e];
    int base = blockIdx.x * 128;
    if (base >= count) return;

    extern __shared__ uint32_t qsm[];
    uint32_t* xs  = qsm;                 /* [128][68] */
    uint32_t* wsT = qsm + 128 * 68;      /* [96][68]  */
    __shared__ int s_a[128];
    int tid = threadIdx.x;
    if (tid < 128) {
        int idx = base + tid; if (idx >= count) idx = count - 1;
        s_a[tid] = g_elist[e * NA + idx];
    }
    int wid = tid >> 5, lane = tid & 31;
    int g = lane >> 2, tig = lane & 3;
    int row_a0 = wid * 16 + g, row_a1 = row_a0 + 8;
    const float* w1 = W1 + (size_t)e * DIM_ * HD_;

    float acc[12][4];
    #pragma unroll
    for (int nn = 0; nn < 12; nn++)
        #pragma unroll
        for (int r = 0; r < 4; r++) acc[nn][r] = 0.f;

    for (int k0 = 0; k0 < DIM_; k0 += 64) {
        __syncthreads();   /* also covers s_a visibility on first iter */
        for (int i = tid; i < 128 * 64; i += 256) {
            int r = i >> 6, k = i & 63;
            int tok = s_a[r] >> 3;
            xs[r * 68 + k] = f2tf32(x[(size_t)tok * DIM_ + k0 + k]);
        }
        for (int i = tid; i < 96 * 64; i += 256) {
            int k = i / 96, c = i % 96;
            wsT[c * 68 + k] = f2tf32(w1[(size_t)(k0 + k) * HD_ + c]);
        }
        __syncthreads();
        #pragma unroll
        for (int kk = 0; kk < 8; kk++) {
            uint32_t a[4];
            a[0] = xs[row_a0 * 68 + kk * 8 + tig];
            a[1] = xs[row_a1 * 68 + kk * 8 + tig];
            a[2] = xs[row_a0 * 68 + kk * 8 + tig + 4];
            a[3] = xs[row_a1 * 68 + kk * 8 + tig + 4];
            #pragma unroll
            for (int nn = 0; nn < 12; nn++) {
                uint32_t bb[2];
                bb[0] = wsT[(nn * 8 + g) * 68 + kk * 8 + tig];
                bb[1] = wsT[(nn * 8 + g) * 68 + kk * 8 + tig + 4];
                mma_tf32(acc[nn], a, bb);
            }
        }
    }

    bool ok0 = (base + row_a0 < count), ok1 = (base + row_a1 < count);
    int a0 = s_a[row_a0], a1 = s_a[row_a1];
    #pragma unroll
    for (int nn = 0; nn < 12; nn++) {
        int c = nn * 8 + tig * 2;
        if (ok0) {
            g_q[(size_t)a0 * HD_ + c]     = acc[nn][0];
            g_q[(size_t)a0 * HD_ + c + 1] = acc[nn][1];
        }
        if (ok1) {
            g_q[(size_t)a1 * HD_ + c]     = acc[nn][2];
            g_q[(size_t)a1 * HD_ + c + 1] = acc[nn][3];
        }
    }
}

/* ---------------- fused flash attention, tf32 mma.sync ---------------------- */
#define QS_STRIDE 100
#define KS_STRIDE 100
#define VS_STRIDE 104
#define PS_STRIDE 68
#define ATTN_SMEM_WORDS (128*QS_STRIDE + 64*KS_STRIDE + 64*VS_STRIDE + 8*16*PS_STRIDE)

__global__ void __launch_bounds__(256, 1) attn_tc_kernel() {
    extern __shared__ uint32_t smu[];
    uint32_t* qs = smu;
    uint32_t* ks = qs + 128 * QS_STRIDE;
    uint32_t* vs = ks + 64 * KS_STRIDE;
    uint32_t* ps = vs + 64 * VS_STRIDE;

    int it = blockIdx.x, bh = blockIdx.y;
    int b = bh >> 3, h = bh & 7;
    int i0 = it * 128;
    int tid  = threadIdx.x;
    int wid  = tid >> 5;
    int lane = tid & 31;
    int g    = lane >> 2;
    int tig  = lane & 3;
    uint32_t* pw = ps + wid * 16 * PS_STRIDE;

    for (int idx = tid; idx < 128 * 96; idx += 256) {
        int i = idx / 96, d = idx % 96;
        qs[i * QS_STRIDE + d] =
            f2tf32(g_q[((size_t)(b * N_ + i0 + i) * H_ + h) * HD_ + d] * SCALE_);
    }

    float m0 = -1e30f, m1 = -1e30f, l0 = 0.f, l1 = 0.f;
    float o_acc[12][4];
    #pragma unroll
    for (int nn = 0; nn < 12; nn++)
        #pragma unroll
        for (int r = 0; r < 4; r++) o_acc[nn][r] = 0.f;

    int row_a0 = wid * 16 + g;
    int row_a1 = wid * 16 + g + 8;

    for (int jt = 0; jt < 16; jt++) {
        int j0 = jt * 64;
        __syncthreads();
        for (int idx = tid; idx < 64 * 96; idx += 256) {
            int j = idx / 96, d = idx % 96;
            int r = b * N_ + j0 + j;
            ks[j * KS_STRIDE + d] = f2tf32(g_k[(size_t)r * HD_ + d]);
            vs[j * VS_STRIDE + d] = f2tf32(g_v[(size_t)r * HD_ + d]);
        }
        __syncthreads();

        float sv[8][4];
        #pragma unroll
        for (int nn = 0; nn < 8; nn++)
            #pragma unroll
            for (int r = 0; r < 4; r++) sv[nn][r] = 0.f;

        #pragma unroll
        for (int kk = 0; kk < 12; kk++) {
            uint32_t a[4];
            a[0] = qs[row_a0 * QS_STRIDE + kk * 8 + tig];
            a[1] = qs[row_a1 * QS_STRIDE + kk * 8 + tig];
            a[2] = qs[row_a0 * QS_STRIDE + kk * 8 + tig + 4];
            a[3] = qs[row_a1 * QS_STRIDE + kk * 8 + tig + 4];
            #pragma unroll
            for (int nn = 0; nn < 8; nn++) {
                uint32_t bb[2];
                bb[0] = ks[(nn * 8 + g) * KS_STRIDE + kk * 8 + tig];
                bb[1] = ks[(nn * 8 + g) * KS_STRIDE + kk * 8 + tig + 4];
                mma_tf32(sv[nn], a, bb);
            }
        }

        float rmax0 = -1e30f, rmax1 = -1e30f;
        #pragma unroll
        for (int nn = 0; nn < 8; nn++) {
            rmax0 = fmaxf(rmax0, fmaxf(sv[nn][0], sv[nn][1]));
            rmax1 = fmaxf(rmax1, fmaxf(sv[nn][2], sv[nn][3]));
        }
        #pragma unroll
        for (int o = 1; o <= 2; o <<= 1) {
            rmax0 = fmaxf(rmax0, __shfl_xor_sync(0xffffffffu, rmax0, o));
            rmax1 = fmaxf(rmax1, __shfl_xor_sync(0xffffffffu, rmax1, o));
        }
        float nm0 = fmaxf(m0, rmax0), nm1 = fmaxf(m1, rmax1);
        float corr0 = __expf(m0 - nm0), corr1 = __expf(m1 - nm1);
        float rs0 = 0.f, rs1 = 0.f;
        #pragma unroll
        for (int nn = 0; nn < 8; nn++) {
            float p00 = __expf(sv[nn][0] - nm0);
            float p01 = __expf(sv[nn][1] - nm0);
            float p10 = __expf(sv[nn][2] - nm1);
            float p11 = __expf(sv[nn][3] - nm1);
            rs0 += p00 + p01; rs1 += p10 + p11;
            int c = nn * 8 + tig * 2;
            pw[g * PS_STRIDE + c]           = f2tf32(p00);
            pw[g * PS_STRIDE + c + 1]       = f2tf32(p01);
            pw[(g + 8) * PS_STRIDE + c]     = f2tf32(p10);
            pw[(g + 8) * PS_STRIDE + c + 1] = f2tf32(p11);
        }
        #pragma unroll
        for (int o = 1; o <= 2; o <<= 1) {
            rs0 += __shfl_xor_sync(0xffffffffu, rs0, o);
            rs1 += __shfl_xor_sync(0xffffffffu, rs1, o);
        }
        l0 = l0 * corr0 + rs0;  m0 = nm0;
        l1 = l1 * corr1 + rs1;  m1 = nm1;
        #pragma unroll
        for (int nn = 0; nn < 12; nn++) {
            o_acc[nn][0] *= corr0; o_acc[nn][1] *= corr0;
            o_acc[nn][2] *= corr1; o_acc[nn][3] *= corr1;
        }
        __syncwarp();

        #pragma unroll
        for (int kk = 0; kk < 8; kk++) {
            uint32_t a[4];
            a[0] = pw[g * PS_STRIDE + kk * 8 + tig];
            a[1] = pw[(g + 8) * PS_STRIDE + kk * 8 + tig];
            a[2] = pw[g * PS_STRIDE + kk * 8 + tig + 4];
            a[3] = pw[(g + 8) * PS_STRIDE + kk * 8 + tig + 4];
            #pragma unroll
            for (int nn = 0; nn < 12; nn++) {
                uint32_t bb[2];
                bb[0] = vs[(kk * 8 + tig) * VS_STRIDE + nn * 8 + g];
                bb[1] = vs[(kk * 8 + tig + 4) * VS_STRIDE + nn * 8 + g];
                mma_tf32(o_acc[nn], a, bb);
            }
        }
        __syncwarp();
    }

    float inv0 = 1.f / l0, inv1 = 1.f / l1;
    int tok0 = b * N_ + i0 + row_a0;
    int tok1 = b * N_ + i0 + row_a1;
    #pragma unroll
    for (int nn = 0; nn < 12; nn++) {
        int c = nn * 8 + tig * 2;
        size_t o0 = ((size_t)tok0 * H_ + h) * HD_ + c;
        size_t o1 = ((size_t)tok1 * H_ + h) * HD_ + c;
        g_o[o0]     = o_acc[nn][0] * inv0;
        g_o[o0 + 1] = o_acc[nn][1] * inv0;
        g_o[o1]     = o_acc[nn][2] * inv1;
        g_o[o1 + 1] = o_acc[nn][3] * inv1;
    }
}

/* ------ stage 1 reduce, tf32 mma: contrib[a] = gate[a]*o[a] @ W2[e] --------- */
/* no atomics — each assignment owns its contrib row                            */
#define RED_SMEM_WORDS (64*100 + 128*100)
__global__ void __launch_bounds__(256) red_tc_kernel(const float* __restrict__ W2) {
    int e = blockIdx.y;
    int count = g_ecount[e];
    int base = blockIdx.x * 64;
    if (base >= count) return;

    extern __shared__ uint32_t rsm[];
    uint32_t* osT = rsm;
    uint32_t* w2T = rsm + 64 * 100;
    __shared__ int s_a[64];

    int tid = threadIdx.x;
    if (tid < 64) {
        int idx = base + tid; if (idx >= count) idx = count - 1;
        s_a[tid] = g_elist[e * NA + idx];
    }
    __syncthreads();

    for (int idx = tid; idx < 64 * 96; idx += 256) {
        int r = idx / 96, d = idx % 96;
        int a = s_a[r];
        osT[r * 100 + d] = f2tf32(g_gate[a] * g_o[(size_t)a * HD_ + d]);
    }

    int wid = tid >> 5, lane = tid & 31;
    int mg = wid & 3, ch = wid >> 2;
    int g = lane >> 2, tig = lane & 3;
    int row_a0 = mg * 16 + g, row_a1 = row_a0 + 8;
    const float* w2 = W2 + (size_t)e * HD_ * DIM_;

    bool ok0 = (base + row_a0 < count), ok1 = (base + row_a1 < count);
    int a0 = s_a[row_a0], a1 = s_a[row_a1];

    for (int ct = 0; ct < 6; ct++) {
        __syncthreads();
        for (int idx = tid; idx < 128 * 96; idx += 256) {
            int k = idx >> 7, c = idx & 127;
            w2T[c * 100 + k] = f2tf32(w2[(size_t)k * DIM_ + ct * 128 + c]);
        }
        __syncthreads();

        float acc[8][4];
        #pragma unroll
        for (int nn = 0; nn < 8; nn++)
            #pragma unroll
            for (int r = 0; r < 4; r++) acc[nn][r] = 0.f;

        #pragma unroll
        for (int kk = 0; kk < 12; kk++) {
            uint32_t a[4];
            a[0] = osT[row_a0 * 100 + kk * 8 + tig];
            a[1] = osT[row_a1 * 100 + kk * 8 + tig];
            a[2] = osT[row_a0 * 100 + kk * 8 + tig + 4];
            a[3] = osT[row_a1 * 100 + kk * 8 + tig + 4];
            #pragma unroll
            for (int nn = 0; nn < 8; nn++) {
                uint32_t bb[2];
                bb[0] = w2T[(ch * 64 + nn * 8 + g) * 100 + kk * 8 + tig];
                bb[1] = w2T[(ch * 64 + nn * 8 + g) * 100 + kk * 8 + tig + 4];
                mma_tf32(acc[nn], a, bb);
            }
        }

        #pragma unroll
        for (int nn = 0; nn < 8; nn++) {
            int c = ct * 128 + ch * 64 + nn * 8 + tig * 2;
            if (ok0)
                *(float2*)&g_contrib[(size_t)a0 * DIM_ + c] =
                    make_float2(acc[nn][0], acc[nn][1]);
            if (ok1)
                *(float2*)&g_contrib[(size_t)a1 * DIM_ + c] =
                    make_float2(acc[nn][2], acc[nn][3]);
        }
    }
}

/* ------ stage 2: out[t][c] = sum_h contrib[t*8+h][c]  (pure streaming) ------ */
__global__ void combine_kernel(float* __restrict__ out) {
    int idx = blockIdx.x * 256 + threadIdx.x;        /* over NT*DIM/4 float4s */
    int per_tok = DIM_ / 4;                          /* 192 */
    int t  = idx / per_tok;
    int c4 = idx - t * per_tok;
    const float4* src = (const float4*)(g_contrib + (size_t)t * H_ * DIM_) + c4;
    float4 s = src[0];
    #pragma unroll
    for (int h = 1; h < H_; h++) {
        float4 v = src[h * per_tok];
        s.x += v.x; s.y += v.y; s.z += v.z; s.w += v.w;
    }
    ((float4*)out)[idx] = s;
}

/* ------------------------------- aux loss ----------------------------------- */
__global__ void aux_kernel(float* __restrict__ out, int out_size) {
    if (threadIdx.x == 0) {
        float mesum = 0.f;
        for (int e = 0; e < E_; e++) mesum += g_me[e];
        float sw = 0.f;
        for (int e = 0; e < E_; e++)
            sw += (g_me[e] / mesum) * ((float)g_ecount[e] / (float)NA);
        sw *= (float)E_;
        float z = g_z / (float)NT;
        float aux = 0.1f * sw + 0.001f * z;
        if (out_size > NT * DIM_) out[out_size - 1] = aux;
    }
}

/* -------------------------------- launch ------------------------------------ */
extern "C" void kernel_launch(void* const* d_in, const int* in_sizes, int n_in,
                              void* d_out, int out_size) {
    const float* x    = (const float*)d_in[0];
    const float* Wg   = (const float*)d_in[1];
    const float* W1   = (const float*)d_in[2];
    const float* W2   = (const float*)d_in[3];
    const float* Wkv  = (const float*)d_in[4];
    const float* bkv  = (const float*)d_in[5];
    const int*   task = (const int*)d_in[6];
    float* out = (float*)d_out;

    cudaFuncSetAttribute(attn_tc_kernel,
                         cudaFuncAttributeMaxDynamicSharedMemorySize,
                         ATTN_SMEM_WORDS * (int)sizeof(uint32_t));
    cudaFuncSetAttribute(red_tc_kernel,
                         cudaFuncAttributeMaxDynamicSharedMemorySize,
                         RED_SMEM_WORDS * (int)sizeof(uint32_t));
    cudaFuncSetAttribute(q_tc_kernel,
                         cudaFuncAttributeMaxDynamicSharedMemorySize,
                         Q_SMEM_WORDS * (int)sizeof(uint32_t));

    zero_kernel<<<1, 32>>>();
    gate_kernel<<<NT / 8, 256>>>(x, Wg, task);
    kv_kernel<<<dim3(NT / 64, 3), 256>>>(x, Wkv, bkv);
    q_tc_kernel<<<dim3(512, E_), 256, Q_SMEM_WORDS * sizeof(uint32_t)>>>(x, W1);
    attn_tc_kernel<<<dim3(8, B_ * H_), 256, ATTN_SMEM_WORDS * sizeof(uint32_t)>>>();
    red_tc_kernel<<<dim3(1024, E_), 256, RED_SMEM_WORDS * sizeof(uint32_t)>>>(W2);
    combine_kernel<<<(NT * DIM_ / 4) / 256, 256>>>(out);
    aux_kernel<<<1, 32>>>(out, out_size);
}

// round 9
// speedup vs baseline: 1.1819x; 1.1819x over previous
#include <cuda_runtime.h>
#include <math.h>
#include <stdint.h>

#define B_    8
#define N_    1024
#define DIM_  768
#define H_    8
#define HD_   96
#define E_    24
#define NT    (B_*N_)      /* 8192 tokens */
#define NA    (NT*H_)      /* 65536 assignments */
#define SCALE_ 0.10206207261596575f  /* 96^-0.5 */

/* ------------------------- scratch (device globals) ------------------------- */
__device__ float    g_gate[NA];
__device__ float    g_me[E_];        /* zero-initialized; aux re-zeroes each run */
__device__ float    g_z;
__device__ int      g_ecount[E_];
__device__ int      g_elist[E_*NA];
__device__ float    g_k[NT*HD_];
__device__ float    g_v[NT*HD_];
__device__ float    g_q[(size_t)NA*HD_];
__device__ float    g_o[(size_t)NA*HD_];
__device__ uint32_t g_xt[(size_t)NT*DIM_];        /* x as tf32 bits          */
__device__ uint32_t g_w1t[(size_t)E_*HD_*DIM_];   /* W1 transposed, tf32 bits */

__device__ __forceinline__ uint32_t f2tf32(float f) {
    uint32_t r;
    asm("cvt.rna.tf32.f32 %0, %1;" : "=r"(r) : "f"(f));
    return r;
}

__device__ __forceinline__ void mma_tf32(float* d, const uint32_t* a, const uint32_t* b) {
    asm("mma.sync.aligned.m16n8k8.row.col.f32.tf32.tf32.f32 "
        "{%0,%1,%2,%3}, {%4,%5,%6,%7}, {%8,%9}, {%0,%1,%2,%3};"
        : "+f"(d[0]), "+f"(d[1]), "+f"(d[2]), "+f"(d[3])
        : "r"(a[0]), "r"(a[1]), "r"(a[2]), "r"(a[3]), "r"(b[0]), "r"(b[1]));
}

__device__ __forceinline__ void red_add_v2(float* addr, float a, float b) {
    asm volatile("red.global.add.v2.f32 [%0], {%1, %2};"
                 :: "l"(addr), "f"(a), "f"(b) : "memory");
}

__device__ __forceinline__ void cp_async16(uint32_t dst_smem, const void* src) {
    asm volatile("cp.async.cg.shared.global [%0], [%1], 16;"
                 :: "r"(dst_smem), "l"(src));
}
__device__ __forceinline__ void cp_commit() {
    asm volatile("cp.async.commit_group;");
}
template<int N> __device__ __forceinline__ void cp_wait() {
    asm volatile("cp.async.wait_group %0;" :: "n"(N));
}

/* ----------- gating + pre-conversion (x->tf32, W1->transposed tf32) --------- */
/* 1024 blocks x 256 threads; warp per token */
__global__ void gate_kernel(const float* __restrict__ x,
                            const float* __restrict__ Wg,
                            const float* __restrict__ W1,
                            const int*   __restrict__ task_p) {
    __shared__ float sme[E_];
    __shared__ float sz;
    __shared__ int   scnt[E_];
    __shared__ int   sbase[E_];
    __shared__ float tile[32][33];
    int tid  = threadIdx.x;
    int warp = tid >> 5;
    int lane = tid & 31;
    int t = blockIdx.x * 8 + warp;   /* always < NT */

    if (tid < E_) { sme[tid] = 0.f; scnt[tid] = 0; }
    if (tid == 0) sz = 0.f;
    __syncthreads();

    int task = *task_p;
    const float* wg = Wg + (size_t)task * DIM_ * E_;
    const float* xr = x + (size_t)t * DIM_;

    float acc = 0.f;
    if (lane < E_) {
        #pragma unroll 4
        for (int d = 0; d < DIM_; d++) acc += xr[d] * wg[d * E_ + lane];
    }
    float logit = (lane < E_) ? acc : -1e30f;

    float m = logit;
    #pragma unroll
    for (int o = 16; o >= 1; o >>= 1) m = fmaxf(m, __shfl_xor_sync(0xffffffffu, m, o));
    float p = (lane < E_) ? expf(logit - m) : 0.f;
    float s = p;
    #pragma unroll
    for (int o = 16; o >= 1; o >>= 1) s += __shfl_xor_sync(0xffffffffu, s, o);
    float prob = p / s;
    float lse = m + logf(s);
    if (lane == 0) atomicAdd(&sz, lse * lse);
    if (lane < E_) atomicAdd(&sme[lane], prob);

    float val = (lane < E_) ? prob : -1.f;
    float sel_g = 0.f; int sel_e = 0;
    #pragma unroll
    for (int it = 0; it < H_; it++) {
        float mm = val;
        #pragma unroll
        for (int o = 16; o >= 1; o >>= 1) mm = fmaxf(mm, __shfl_xor_sync(0xffffffffu, mm, o));
        unsigned msk = __ballot_sync(0xffffffffu, val == mm);
        int src = __ffs(msk) - 1;
        if (lane == src) val = -1.f;
        if (lane == it) { sel_e = src; sel_g = mm; }
    }
    float gv = (lane < H_) ? sel_g : 0.f;
    #pragma unroll
    for (int o = 16; o >= 1; o >>= 1) gv += __shfl_xor_sync(0xffffffffu, gv, o);
    float denom = gv + 1e-6f;

    int pos = 0;
    if (lane < H_) pos = atomicAdd(&scnt[sel_e], 1);
    __syncthreads();
    if (tid < E_) sbase[tid] = atomicAdd(&g_ecount[tid], scnt[tid]);
    __syncthreads();
    if (lane < H_) {
        int a = t * H_ + lane;
        g_gate[a] = sel_g / denom;
        g_elist[sel_e * NA + sbase[sel_e] + pos] = a;
    }
    if (tid < E_) atomicAdd(&g_me[tid], sme[tid]);
    if (tid == 0) atomicAdd(&g_z, sz);

    /* ---- pre-convert x -> g_xt (tf32 bits), coalesced float4 ---- */
    {
        const float4* xin = (const float4*)x;
        uint4* xout = (uint4*)g_xt;
        int base4 = blockIdx.x * 1536;      /* NT*DIM/4/1024 */
        for (int i = tid; i < 1536; i += 256) {
            float4 v = xin[base4 + i];
            uint4 u;
            u.x = f2tf32(v.x); u.y = f2tf32(v.y);
            u.z = f2tf32(v.z); u.w = f2tf32(v.w);
            xout[base4 + i] = u;
        }
    }

    /* ---- pre-convert W1 -> g_w1t [e][c][k], tf32, 32x32 smem tiles ---- */
    /* tiles: 24 experts x 24 k-tiles x 3 c-tiles = 1728 */
    int ty = tid >> 5, tx8 = tid & 31;
    for (int tix = blockIdx.x; tix < 1728; tix += 1024) {
        int e  = tix / 72;
        int rem = tix % 72;
        int kt = rem / 3, ct = rem % 3;
        __syncthreads();
        for (int r = ty; r < 32; r += 8)
            tile[r][tx8] = W1[((size_t)e * DIM_ + kt * 32 + r) * HD_ + ct * 32 + tx8];
        __syncthreads();
        for (int r = ty; r < 32; r += 8)
            g_w1t[((size_t)e * HD_ + ct * 32 + r) * DIM_ + kt * 32 + tx8] =
                f2tf32(tile[tx8][r]);
    }
}

/* ------------------------ zero output (for atomic reduce) ------------------- */
__global__ void zero_out_kernel(float* __restrict__ out, int n) {
    int i = blockIdx.x * 256 + threadIdx.x;
    if (i < n) out[i] = 0.f;
}

/* ----------------- kv projection (R2 SIMT, measured 98.7us) ----------------- */
__global__ void kv_kernel(const float* __restrict__ x,
                          const float* __restrict__ Wkv,
                          const float* __restrict__ bkv) {
    __shared__ float xsT[32][68];
    __shared__ float ws[32][68];
    int r0 = blockIdx.x * 64;
    int c0 = blockIdx.y * 64;
    int tid = threadIdx.x;
    int ty = tid >> 4, tx = tid & 15;
    float acc[4][4] = {};

    for (int k0 = 0; k0 < DIM_; k0 += 32) {
        for (int i = tid; i < 64 * 32; i += 256) {
            int r = i >> 5, k = i & 31;
            xsT[k][r] = x[(size_t)(r0 + r) * DIM_ + k0 + k];
        }
        for (int i = tid; i < 32 * 64; i += 256) {
            int k = i >> 6, c = i & 63;
            ws[k][c] = Wkv[(size_t)(k0 + k) * (2 * HD_) + c0 + c];
        }
        __syncthreads();
        #pragma unroll
        for (int k = 0; k < 32; k++) {
            float4 a4 = *(const float4*)&xsT[k][ty * 4];
            float4 b4 = *(const float4*)&ws[k][tx * 4];
            float av[4] = {a4.x, a4.y, a4.z, a4.w};
            float bv[4] = {b4.x, b4.y, b4.z, b4.w};
            #pragma unroll
            for (int i = 0; i < 4; i++)
                #pragma unroll
                for (int j = 0; j < 4; j++) acc[i][j] += av[i] * bv[j];
        }
        __syncthreads();
    }
    #pragma unroll
    for (int i = 0; i < 4; i++) {
        int r = r0 + ty * 4 + i;
        #pragma unroll
        for (int j = 0; j < 4; j++) {
            int c = c0 + tx * 4 + j;
            float v = acc[i][j] + bkv[c];
            if (c < HD_) g_k[(size_t)r * HD_ + c]          = v;
            else         g_v[(size_t)r * HD_ + (c - HD_)]  = v;
        }
    }
}

/* ------- grouped q projection: cp.async double-buffered tf32 mma ------------ */
/* tile 128 assignments x 96 cols, K-chunk 32, 24 chunks; grid (512, 24)        */
#define Q_SMEM_WORDS (2*128*36 + 2*96*36)    /* 64512 bytes */
__global__ void __launch_bounds__(256) q_tc_kernel() {
    int e = blockIdx.y;
    int count = g_ecount[e];
    int base = blockIdx.x * 128;
    if (base >= count) return;

    extern __shared__ uint32_t qsm[];
    uint32_t* xs = qsm;                    /* [2][128][36] */
    uint32_t* ws = qsm + 2 * 128 * 36;     /* [2][96][36]  */
    __shared__ int s_a[128];
    int tid = threadIdx.x;
    if (tid < 128) {
        int idx = base + tid; if (idx >= count) idx = count - 1;
        s_a[tid] = g_elist[e * NA + idx];
    }
    __syncthreads();

    uint32_t xs_smem = (uint32_t)__cvta_generic_to_shared(xs);
    uint32_t ws_smem = (uint32_t)__cvta_generic_to_shared(ws);
    const uint32_t* w1t = g_w1t + (size_t)e * HD_ * DIM_;

    int wid = tid >> 5, lane = tid & 31;
    int g = lane >> 2, tig = lane & 3;
    int row_a0 = wid * 16 + g, row_a1 = row_a0 + 8;

    float acc[12][4];
    #pragma unroll
    for (int nn = 0; nn < 12; nn++)
        #pragma unroll
        for (int r = 0; r < 4; r++) acc[nn][r] = 0.f;

    /* fill chunk (K=32) into buffer bi via cp.async (16B units) */
    auto fill = [&](int bi, int k0) {
        uint32_t xb = xs_smem + bi * (128 * 36 * 4);
        uint32_t wb = ws_smem + bi * (96 * 36 * 4);
        #pragma unroll
        for (int j = 0; j < 4; j++) {              /* 128 rows x 8 segs = 1024 */
            int item = tid + 256 * j;
            int r = item >> 3, seg = item & 7;
            int tok = s_a[r] >> 3;
            cp_async16(xb + (r * 36 + seg * 4) * 4,
                       g_xt + (size_t)tok * DIM_ + k0 + seg * 4);
        }
        #pragma unroll
        for (int j = 0; j < 3; j++) {              /* 96 rows x 8 segs = 768 */
            int item = tid + 256 * j;
            int c = item >> 3, seg = item & 7;
            cp_async16(wb + (c * 36 + seg * 4) * 4,
                       w1t + (size_t)c * DIM_ + k0 + seg * 4);
        }
        cp_commit();
    };

    fill(0, 0);
    for (int c = 0; c < 24; c++) {
        if (c < 23) fill((c + 1) & 1, (c + 1) * 32);
        if (c < 23) cp_wait<1>(); else cp_wait<0>();
        __syncthreads();
        uint32_t* xsb = xs + (c & 1) * 128 * 36;
        uint32_t* wsb = ws + (c & 1) * 96 * 36;
        #pragma unroll
        for (int kk = 0; kk < 4; kk++) {
            uint32_t a[4];
            a[0] = xsb[row_a0 * 36 + kk * 8 + tig];
            a[1] = xsb[row_a1 * 36 + kk * 8 + tig];
            a[2] = xsb[row_a0 * 36 + kk * 8 + tig + 4];
            a[3] = xsb[row_a1 * 36 + kk * 8 + tig + 4];
            #pragma unroll
            for (int nn = 0; nn < 12; nn++) {
                uint32_t bb[2];
                bb[0] = wsb[(nn * 8 + g) * 36 + kk * 8 + tig];
                bb[1] = wsb[(nn * 8 + g) * 36 + kk * 8 + tig + 4];
                mma_tf32(acc[nn], a, bb);
            }
        }
        __syncthreads();
    }

    bool ok0 = (base + row_a0 < count), ok1 = (base + row_a1 < count);
    int a0 = s_a[row_a0], a1 = s_a[row_a1];
    #pragma unroll
    for (int nn = 0; nn < 12; nn++) {
        int c = nn * 8 + tig * 2;
        if (ok0) {
            g_q[(size_t)a0 * HD_ + c]     = acc[nn][0];
            g_q[(size_t)a0 * HD_ + c + 1] = acc[nn][1];
        }
        if (ok1) {
            g_q[(size_t)a1 * HD_ + c]     = acc[nn][2];
            g_q[(size_t)a1 * HD_ + c + 1] = acc[nn][3];
        }
    }
}

/* ---------------- fused flash attention, tf32 mma.sync ---------------------- */
#define QS_STRIDE 100
#define KS_STRIDE 100
#define VS_STRIDE 104
#define PS_STRIDE 68
#define ATTN_SMEM_WORDS (128*QS_STRIDE + 64*KS_STRIDE + 64*VS_STRIDE + 8*16*PS_STRIDE)

__global__ void __launch_bounds__(256, 1) attn_tc_kernel() {
    extern __shared__ uint32_t smu[];
    uint32_t* qs = smu;
    uint32_t* ks = qs + 128 * QS_STRIDE;
    uint32_t* vs = ks + 64 * KS_STRIDE;
    uint32_t* ps = vs + 64 * VS_STRIDE;

    int it = blockIdx.x, bh = blockIdx.y;
    int b = bh >> 3, h = bh & 7;
    int i0 = it * 128;
    int tid  = threadIdx.x;
    int wid  = tid >> 5;
    int lane = tid & 31;
    int g    = lane >> 2;
    int tig  = lane & 3;
    uint32_t* pw = ps + wid * 16 * PS_STRIDE;

    for (int idx = tid; idx < 128 * 96; idx += 256) {
        int i = idx / 96, d = idx % 96;
        qs[i * QS_STRIDE + d] =
            f2tf32(g_q[((size_t)(b * N_ + i0 + i) * H_ + h) * HD_ + d] * SCALE_);
    }

    float m0 = -1e30f, m1 = -1e30f, l0 = 0.f, l1 = 0.f;
    float o_acc[12][4];
    #pragma unroll
    for (int nn = 0; nn < 12; nn++)
        #pragma unroll
        for (int r = 0; r < 4; r++) o_acc[nn][r] = 0.f;

    int row_a0 = wid * 16 + g;
    int row_a1 = wid * 16 + g + 8;

    for (int jt = 0; jt < 16; jt++) {
        int j0 = jt * 64;
        __syncthreads();
        for (int idx = tid; idx < 64 * 96; idx += 256) {
            int j = idx / 96, d = idx % 96;
            int r = b * N_ + j0 + j;
            ks[j * KS_STRIDE + d] = f2tf32(g_k[(size_t)r * HD_ + d]);
            vs[j * VS_STRIDE + d] = f2tf32(g_v[(size_t)r * HD_ + d]);
        }
        __syncthreads();

        float sv[8][4];
        #pragma unroll
        for (int nn = 0; nn < 8; nn++)
            #pragma unroll
            for (int r = 0; r < 4; r++) sv[nn][r] = 0.f;

        #pragma unroll
        for (int kk = 0; kk < 12; kk++) {
            uint32_t a[4];
            a[0] = qs[row_a0 * QS_STRIDE + kk * 8 + tig];
            a[1] = qs[row_a1 * QS_STRIDE + kk * 8 + tig];
            a[2] = qs[row_a0 * QS_STRIDE + kk * 8 + tig + 4];
            a[3] = qs[row_a1 * QS_STRIDE + kk * 8 + tig + 4];
            #pragma unroll
            for (int nn = 0; nn < 8; nn++) {
                uint32_t bb[2];
                bb[0] = ks[(nn * 8 + g) * KS_STRIDE + kk * 8 + tig];
                bb[1] = ks[(nn * 8 + g) * KS_STRIDE + kk * 8 + tig + 4];
                mma_tf32(sv[nn], a, bb);
            }
        }

        float rmax0 = -1e30f, rmax1 = -1e30f;
        #pragma unroll
        for (int nn = 0; nn < 8; nn++) {
            rmax0 = fmaxf(rmax0, fmaxf(sv[nn][0], sv[nn][1]));
            rmax1 = fmaxf(rmax1, fmaxf(sv[nn][2], sv[nn][3]));
        }
        #pragma unroll
        for (int o = 1; o <= 2; o <<= 1) {
            rmax0 = fmaxf(rmax0, __shfl_xor_sync(0xffffffffu, rmax0, o));
            rmax1 = fmaxf(rmax1, __shfl_xor_sync(0xffffffffu, rmax1, o));
        }
        float nm0 = fmaxf(m0, rmax0), nm1 = fmaxf(m1, rmax1);
        float corr0 = __expf(m0 - nm0), corr1 = __expf(m1 - nm1);
        float rs0 = 0.f, rs1 = 0.f;
        #pragma unroll
        for (int nn = 0; nn < 8; nn++) {
            float p00 = __expf(sv[nn][0] - nm0);
            float p01 = __expf(sv[nn][1] - nm0);
            float p10 = __expf(sv[nn][2] - nm1);
            float p11 = __expf(sv[nn][3] - nm1);
            rs0 += p00 + p01; rs1 += p10 + p11;
            int c = nn * 8 + tig * 2;
            pw[g * PS_STRIDE + c]           = f2tf32(p00);
            pw[g * PS_STRIDE + c + 1]       = f2tf32(p01);
            pw[(g + 8) * PS_STRIDE + c]     = f2tf32(p10);
            pw[(g + 8) * PS_STRIDE + c + 1] = f2tf32(p11);
        }
        #pragma unroll
        for (int o = 1; o <= 2; o <<= 1) {
            rs0 += __shfl_xor_sync(0xffffffffu, rs0, o);
            rs1 += __shfl_xor_sync(0xffffffffu, rs1, o);
        }
        l0 = l0 * corr0 + rs0;  m0 = nm0;
        l1 = l1 * corr1 + rs1;  m1 = nm1;
        #pragma unroll
        for (int nn = 0; nn < 12; nn++) {
            o_acc[nn][0] *= corr0; o_acc[nn][1] *= corr0;
            o_acc[nn][2] *= corr1; o_acc[nn][3] *= corr1;
        }
        __syncwarp();

        #pragma unroll
        for (int kk = 0; kk < 8; kk++) {
            uint32_t a[4];
            a[0] = pw[g * PS_STRIDE + kk * 8 + tig];
            a[1] = pw[(g + 8) * PS_STRIDE + kk * 8 + tig];
            a[2] = pw[g * PS_STRIDE + kk * 8 + tig + 4];
            a[3] = pw[(g + 8) * PS_STRIDE + kk * 8 + tig + 4];
            #pragma unroll
            for (int nn = 0; nn < 12; nn++) {
                uint32_t bb[2];
                bb[0] = vs[(kk * 8 + tig) * VS_STRIDE + nn * 8 + g];
                bb[1] = vs[(kk * 8 + tig + 4) * VS_STRIDE + nn * 8 + g];
                mma_tf32(o_acc[nn], a, bb);
            }
        }
        __syncwarp();
    }

    float inv0 = 1.f / l0, inv1 = 1.f / l1;
    int tok0 = b * N_ + i0 + row_a0;
    int tok1 = b * N_ + i0 + row_a1;
    #pragma unroll
    for (int nn = 0; nn < 12; nn++) {
        int c = nn * 8 + tig * 2;
        size_t o0 = ((size_t)tok0 * H_ + h) * HD_ + c;
        size_t o1 = ((size_t)tok1 * H_ + h) * HD_ + c;
        g_o[o0]     = o_acc[nn][0] * inv0;
        g_o[o0 + 1] = o_acc[nn][1] * inv0;
        g_o[o1]     = o_acc[nn][2] * inv1;
        g_o[o1 + 1] = o_acc[nn][3] * inv1;
    }
}

/* ------ grouped reduce, tf32 mma: out[t] += gate[a]*o[a] @ W2[e] (v2 red) --- */
#define RED_SMEM_WORDS (64*100 + 128*100)
__global__ void __launch_bounds__(256) red_tc_kernel(const float* __restrict__ W2,
                                                     float* __restrict__ out) {
    int e = blockIdx.y;
    int count = g_ecount[e];
    int base = blockIdx.x * 64;
    if (base >= count) return;

    extern __shared__ uint32_t rsm[];
    uint32_t* osT = rsm;
    uint32_t* w2T = rsm + 64 * 100;
    __shared__ int s_a[64];

    int tid = threadIdx.x;
    if (tid < 64) {
        int idx = base + tid; if (idx >= count) idx = count - 1;
        s_a[tid] = g_elist[e * NA + idx];
    }
    __syncthreads();

    for (int idx = tid; idx < 64 * 96; idx += 256) {
        int r = idx / 96, d = idx % 96;
        int a = s_a[r];
        osT[r * 100 + d] = f2tf32(g_gate[a] * g_o[(size_t)a * HD_ + d]);
    }

    int wid = tid >> 5, lane = tid & 31;
    int mg = wid & 3, ch = wid >> 2;
    int g = lane >> 2, tig = lane & 3;
    int row_a0 = mg * 16 + g, row_a1 = row_a0 + 8;
    const float* w2 = W2 + (size_t)e * HD_ * DIM_;

    bool ok0 = (base + row_a0 < count), ok1 = (base + row_a1 < count);
    int t0 = s_a[row_a0] >> 3, t1 = s_a[row_a1] >> 3;

    for (int ct = 0; ct < 6; ct++) {
        __syncthreads();
        for (int idx = tid; idx < 128 * 96; idx += 256) {
            int k = idx >> 7, c = idx & 127;
            w2T[c * 100 + k] = f2tf32(w2[(size_t)k * DIM_ + ct * 128 + c]);
        }
        __syncthreads();

        float acc[8][4];
        #pragma unroll
        for (int nn = 0; nn < 8; nn++)
            #pragma unroll
            for (int r = 0; r < 4; r++) acc[nn][r] = 0.f;

        #pragma unroll
        for (int kk = 0; kk < 12; kk++) {
            uint32_t a[4];
            a[0] = osT[row_a0 * 100 + kk * 8 + tig];
            a[1] = osT[row_a1 * 100 + kk * 8 + tig];
            a[2] = osT[row_a0 * 100 + kk * 8 + tig + 4];
            a[3] = osT[row_a1 * 100 + kk * 8 + tig + 4];
            #pragma unroll
            for (int nn = 0; nn < 8; nn++) {
                uint32_t bb[2];
                bb[0] = w2T[(ch * 64 + nn * 8 + g) * 100 + kk * 8 + tig];
                bb[1] = w2T[(ch * 64 + nn * 8 + g) * 100 + kk * 8 + tig + 4];
                mma_tf32(acc[nn], a, bb);
            }
        }

        #pragma unroll
        for (int nn = 0; nn < 8; nn++) {
            int c = ct * 128 + ch * 64 + nn * 8 + tig * 2;
            if (ok0) red_add_v2(&out[(size_t)t0 * DIM_ + c], acc[nn][0], acc[nn][1]);
            if (ok1) red_add_v2(&out[(size_t)t1 * DIM_ + c], acc[nn][2], acc[nn][3]);
        }
    }
}

/* ------------- aux loss + restore zeroed gating state for next run ---------- */
__global__ void aux_kernel(float* __restrict__ out, int out_size) {
    int tid = threadIdx.x;
    if (tid == 0) {
        float mesum = 0.f;
        for (int e = 0; e < E_; e++) mesum += g_me[e];
        float sw = 0.f;
        for (int e = 0; e < E_; e++)
            sw += (g_me[e] / mesum) * ((float)g_ecount[e] / (float)NA);
        sw *= (float)E_;
        float z = g_z / (float)NT;
        float aux = 0.1f * sw + 0.001f * z;
        if (out_size > NT * DIM_) out[out_size - 1] = aux;
    }
    __syncwarp();
    if (tid < E_) { g_me[tid] = 0.f; g_ecount[tid] = 0; }
    if (tid == 0) g_z = 0.f;
}

/* -------------------------------- launch ------------------------------------ */
extern "C" void kernel_launch(void* const* d_in, const int* in_sizes, int n_in,
                              void* d_out, int out_size) {
    const float* x    = (const float*)d_in[0];
    const float* Wg   = (const float*)d_in[1];
    const float* W1   = (const float*)d_in[2];
    const float* W2   = (const float*)d_in[3];
    const float* Wkv  = (const float*)d_in[4];
    const float* bkv  = (const float*)d_in[5];
    const int*   task = (const int*)d_in[6];
    float* out = (float*)d_out;

    cudaFuncSetAttribute(attn_tc_kernel,
                         cudaFuncAttributeMaxDynamicSharedMemorySize,
                         ATTN_SMEM_WORDS * (int)sizeof(uint32_t));
    cudaFuncSetAttribute(red_tc_kernel,
                         cudaFuncAttributeMaxDynamicSharedMemorySize,
                         RED_SMEM_WORDS * (int)sizeof(uint32_t));
    cudaFuncSetAttribute(q_tc_kernel,
                         cudaFuncAttributeMaxDynamicSharedMemorySize,
                         Q_SMEM_WORDS * (int)sizeof(uint32_t));

    gate_kernel<<<NT / 8, 256>>>(x, Wg, W1, task);                               /* #1 */
    kv_kernel<<<dim3(NT / 64, 3), 256>>>(x, Wkv, bkv);                           /* #2 */
    q_tc_kernel<<<dim3(512, E_), 256, Q_SMEM_WORDS * sizeof(uint32_t)>>>();      /* #3 */
    attn_tc_kernel<<<dim3(8, B_ * H_), 256,
                     ATTN_SMEM_WORDS * sizeof(uint32_t)>>>();                    /* #4 */
    zero_out_kernel<<<(out_size + 255) / 256, 256>>>(out, out_size);             /* #5 */
    red_tc_kernel<<<dim3(1024, E_), 256,
                    RED_SMEM_WORDS * sizeof(uint32_t)>>>(W2, out);               /* #6 */
    aux_kernel<<<1, 32>>>(out, out_size);                                        /* #7 */
}

// round 10
// speedup vs baseline: 1.4019x; 1.1862x over previous
#include <cuda_runtime.h>
#include <math.h>
#include <stdint.h>

#define B_    8
#define N_    1024
#define DIM_  768
#define H_    8
#define HD_   96
#define E_    24
#define NT    (B_*N_)      /* 8192 tokens */
#define NA    (NT*H_)      /* 65536 assignments */
#define SCALE_ 0.10206207261596575f  /* 96^-0.5 */

/* ------------------------- scratch (device globals) ------------------------- */
__device__ float    g_gate[NA];
__device__ float    g_me[E_];        /* zero-initialized; aux re-zeroes each run */
__device__ float    g_z;
__device__ int      g_ecount[E_];
__device__ int      g_elist[E_*NA];
__device__ uint32_t g_kt[NT*HD_];                 /* k as tf32 bits           */
__device__ uint32_t g_vt[NT*HD_];                 /* v as tf32 bits           */
__device__ uint32_t g_qt[(size_t)NA*HD_];         /* q*scale as tf32 bits     */
__device__ float    g_o[(size_t)NA*HD_];
__device__ uint32_t g_xt[(size_t)NT*DIM_];        /* x as tf32 bits           */
__device__ uint32_t g_w1t[(size_t)E_*HD_*DIM_];   /* W1 transposed, tf32 bits */

__device__ __forceinline__ uint32_t f2tf32(float f) {
    uint32_t r;
    asm("cvt.rna.tf32.f32 %0, %1;" : "=r"(r) : "f"(f));
    return r;
}

__device__ __forceinline__ void mma_tf32(float* d, const uint32_t* a, const uint32_t* b) {
    asm("mma.sync.aligned.m16n8k8.row.col.f32.tf32.tf32.f32 "
        "{%0,%1,%2,%3}, {%4,%5,%6,%7}, {%8,%9}, {%0,%1,%2,%3};"
        : "+f"(d[0]), "+f"(d[1]), "+f"(d[2]), "+f"(d[3])
        : "r"(a[0]), "r"(a[1]), "r"(a[2]), "r"(a[3]), "r"(b[0]), "r"(b[1]));
}

__device__ __forceinline__ void red_add_v2(float* addr, float a, float b) {
    asm volatile("red.global.add.v2.f32 [%0], {%1, %2};"
                 :: "l"(addr), "f"(a), "f"(b) : "memory");
}

__device__ __forceinline__ void cp_async16(uint32_t dst_smem, const void* src) {
    asm volatile("cp.async.cg.shared.global [%0], [%1], 16;"
                 :: "r"(dst_smem), "l"(src));
}
__device__ __forceinline__ void cp_commit() {
    asm volatile("cp.async.commit_group;");
}
template<int N> __device__ __forceinline__ void cp_wait() {
    asm volatile("cp.async.wait_group %0;" :: "n"(N));
}

/* ----------- gating + pre-conversion (x->tf32, W1->transposed tf32) --------- */
__global__ void gate_kernel(const float* __restrict__ x,
                            const float* __restrict__ Wg,
                            const float* __restrict__ W1,
                            const int*   __restrict__ task_p) {
    __shared__ float sme[E_];
    __shared__ float sz;
    __shared__ int   scnt[E_];
    __shared__ int   sbase[E_];
    __shared__ float tile[32][33];
    int tid  = threadIdx.x;
    int warp = tid >> 5;
    int lane = tid & 31;
    int t = blockIdx.x * 8 + warp;

    if (tid < E_) { sme[tid] = 0.f; scnt[tid] = 0; }
    if (tid == 0) sz = 0.f;
    __syncthreads();

    int task = *task_p;
    const float* wg = Wg + (size_t)task * DIM_ * E_;
    const float* xr = x + (size_t)t * DIM_;

    float acc = 0.f;
    if (lane < E_) {
        #pragma unroll 4
        for (int d = 0; d < DIM_; d++) acc += xr[d] * wg[d * E_ + lane];
    }
    float logit = (lane < E_) ? acc : -1e30f;

    float m = logit;
    #pragma unroll
    for (int o = 16; o >= 1; o >>= 1) m = fmaxf(m, __shfl_xor_sync(0xffffffffu, m, o));
    float p = (lane < E_) ? expf(logit - m) : 0.f;
    float s = p;
    #pragma unroll
    for (int o = 16; o >= 1; o >>= 1) s += __shfl_xor_sync(0xffffffffu, s, o);
    float prob = p / s;
    float lse = m + logf(s);
    if (lane == 0) atomicAdd(&sz, lse * lse);
    if (lane < E_) atomicAdd(&sme[lane], prob);

    float val = (lane < E_) ? prob : -1.f;
    float sel_g = 0.f; int sel_e = 0;
    #pragma unroll
    for (int it = 0; it < H_; it++) {
        float mm = val;
        #pragma unroll
        for (int o = 16; o >= 1; o >>= 1) mm = fmaxf(mm, __shfl_xor_sync(0xffffffffu, mm, o));
        unsigned msk = __ballot_sync(0xffffffffu, val == mm);
        int src = __ffs(msk) - 1;
        if (lane == src) val = -1.f;
        if (lane == it) { sel_e = src; sel_g = mm; }
    }
    float gv = (lane < H_) ? sel_g : 0.f;
    #pragma unroll
    for (int o = 16; o >= 1; o >>= 1) gv += __shfl_xor_sync(0xffffffffu, gv, o);
    float denom = gv + 1e-6f;

    int pos = 0;
    if (lane < H_) pos = atomicAdd(&scnt[sel_e], 1);
    __syncthreads();
    if (tid < E_) sbase[tid] = atomicAdd(&g_ecount[tid], scnt[tid]);
    __syncthreads();
    if (lane < H_) {
        int a = t * H_ + lane;
        g_gate[a] = sel_g / denom;
        g_elist[sel_e * NA + sbase[sel_e] + pos] = a;
    }
    if (tid < E_) atomicAdd(&g_me[tid], sme[tid]);
    if (tid == 0) atomicAdd(&g_z, sz);

    /* ---- pre-convert x -> g_xt (tf32 bits) ---- */
    {
        const float4* xin = (const float4*)x;
        uint4* xout = (uint4*)g_xt;
        int base4 = blockIdx.x * 1536;
        for (int i = tid; i < 1536; i += 256) {
            float4 v = xin[base4 + i];
            uint4 u;
            u.x = f2tf32(v.x); u.y = f2tf32(v.y);
            u.z = f2tf32(v.z); u.w = f2tf32(v.w);
            xout[base4 + i] = u;
        }
    }

    /* ---- pre-convert W1 -> g_w1t [e][c][k], tf32, 32x32 smem tiles ---- */
    int ty = tid >> 5, tx8 = tid & 31;
    for (int tix = blockIdx.x; tix < 1728; tix += 1024) {
        int e  = tix / 72;
        int rem = tix % 72;
        int kt = rem / 3, ct = rem % 3;
        __syncthreads();
        for (int r = ty; r < 32; r += 8)
            tile[r][tx8] = W1[((size_t)e * DIM_ + kt * 32 + r) * HD_ + ct * 32 + tx8];
        __syncthreads();
        for (int r = ty; r < 32; r += 8)
            g_w1t[((size_t)e * HD_ + ct * 32 + r) * DIM_ + kt * 32 + tx8] =
                f2tf32(tile[tx8][r]);
    }
}

/* ------------------------ zero output (for atomic reduce) ------------------- */
__global__ void zero_out_kernel(float* __restrict__ out, int n) {
    int i = blockIdx.x * 256 + threadIdx.x;
    if (i < n) out[i] = 0.f;
}

/* ------- kv projection (SIMT) -> tf32 bit outputs g_kt / g_vt --------------- */
__global__ void kv_kernel(const float* __restrict__ x,
                          const float* __restrict__ Wkv,
                          const float* __restrict__ bkv) {
    __shared__ float xsT[32][68];
    __shared__ float ws[32][68];
    int r0 = blockIdx.x * 64;
    int c0 = blockIdx.y * 64;
    int tid = threadIdx.x;
    int ty = tid >> 4, tx = tid & 15;
    float acc[4][4] = {};

    for (int k0 = 0; k0 < DIM_; k0 += 32) {
        for (int i = tid; i < 64 * 32; i += 256) {
            int r = i >> 5, k = i & 31;
            xsT[k][r] = x[(size_t)(r0 + r) * DIM_ + k0 + k];
        }
        for (int i = tid; i < 32 * 64; i += 256) {
            int k = i >> 6, c = i & 63;
            ws[k][c] = Wkv[(size_t)(k0 + k) * (2 * HD_) + c0 + c];
        }
        __syncthreads();
        #pragma unroll
        for (int k = 0; k < 32; k++) {
            float4 a4 = *(const float4*)&xsT[k][ty * 4];
            float4 b4 = *(const float4*)&ws[k][tx * 4];
            float av[4] = {a4.x, a4.y, a4.z, a4.w};
            float bv[4] = {b4.x, b4.y, b4.z, b4.w};
            #pragma unroll
            for (int i = 0; i < 4; i++)
                #pragma unroll
                for (int j = 0; j < 4; j++) acc[i][j] += av[i] * bv[j];
        }
        __syncthreads();
    }
    #pragma unroll
    for (int i = 0; i < 4; i++) {
        int r = r0 + ty * 4 + i;
        #pragma unroll
        for (int j = 0; j < 4; j++) {
            int c = c0 + tx * 4 + j;
            uint32_t v = f2tf32(acc[i][j] + bkv[c]);
            if (c < HD_) g_kt[(size_t)r * HD_ + c]          = v;
            else         g_vt[(size_t)r * HD_ + (c - HD_)]  = v;
        }
    }
}

/* ------- grouped q projection: cp.async double-buffered tf32 mma ------------ */
#define Q_SMEM_WORDS (2*128*36 + 2*96*36)
__global__ void __launch_bounds__(256) q_tc_kernel() {
    int e = blockIdx.y;
    int count = g_ecount[e];
    int base = blockIdx.x * 128;
    if (base >= count) return;

    extern __shared__ uint32_t qsm[];
    uint32_t* xs = qsm;
    uint32_t* ws = qsm + 2 * 128 * 36;
    __shared__ int s_a[128];
    int tid = threadIdx.x;
    if (tid < 128) {
        int idx = base + tid; if (idx >= count) idx = count - 1;
        s_a[tid] = g_elist[e * NA + idx];
    }
    __syncthreads();

    uint32_t xs_smem = (uint32_t)__cvta_generic_to_shared(xs);
    uint32_t ws_smem = (uint32_t)__cvta_generic_to_shared(ws);
    const uint32_t* w1t = g_w1t + (size_t)e * HD_ * DIM_;

    int wid = tid >> 5, lane = tid & 31;
    int g = lane >> 2, tig = lane & 3;
    int row_a0 = wid * 16 + g, row_a1 = row_a0 + 8;

    float acc[12][4];
    #pragma unroll
    for (int nn = 0; nn < 12; nn++)
        #pragma unroll
        for (int r = 0; r < 4; r++) acc[nn][r] = 0.f;

    auto fill = [&](int bi, int k0) {
        uint32_t xb = xs_smem + bi * (128 * 36 * 4);
        uint32_t wb = ws_smem + bi * (96 * 36 * 4);
        #pragma unroll
        for (int j = 0; j < 4; j++) {
            int item = tid + 256 * j;
            int r = item >> 3, seg = item & 7;
            int tok = s_a[r] >> 3;
            cp_async16(xb + (r * 36 + seg * 4) * 4,
                       g_xt + (size_t)tok * DIM_ + k0 + seg * 4);
        }
        #pragma unroll
        for (int j = 0; j < 3; j++) {
            int item = tid + 256 * j;
            int c = item >> 3, seg = item & 7;
            cp_async16(wb + (c * 36 + seg * 4) * 4,
                       w1t + (size_t)c * DIM_ + k0 + seg * 4);
        }
        cp_commit();
    };

    fill(0, 0);
    for (int c = 0; c < 24; c++) {
        if (c < 23) fill((c + 1) & 1, (c + 1) * 32);
        if (c < 23) cp_wait<1>(); else cp_wait<0>();
        __syncthreads();
        uint32_t* xsb = xs + (c & 1) * 128 * 36;
        uint32_t* wsb = ws + (c & 1) * 96 * 36;
        #pragma unroll
        for (int kk = 0; kk < 4; kk++) {
            uint32_t a[4];
            a[0] = xsb[row_a0 * 36 + kk * 8 + tig];
            a[1] = xsb[row_a1 * 36 + kk * 8 + tig];
            a[2] = xsb[row_a0 * 36 + kk * 8 + tig + 4];
            a[3] = xsb[row_a1 * 36 + kk * 8 + tig + 4];
            #pragma unroll
            for (int nn = 0; nn < 12; nn++) {
                uint32_t bb[2];
                bb[0] = wsb[(nn * 8 + g) * 36 + kk * 8 + tig];
                bb[1] = wsb[(nn * 8 + g) * 36 + kk * 8 + tig + 4];
                mma_tf32(acc[nn], a, bb);
            }
        }
        __syncthreads();
    }

    bool ok0 = (base + row_a0 < count), ok1 = (base + row_a1 < count);
    int a0 = s_a[row_a0], a1 = s_a[row_a1];
    #pragma unroll
    for (int nn = 0; nn < 12; nn++) {
        int c = nn * 8 + tig * 2;
        if (ok0) {   /* pre-scaled tf32 q for attention */
            g_qt[(size_t)a0 * HD_ + c]     = f2tf32(acc[nn][0] * SCALE_);
            g_qt[(size_t)a0 * HD_ + c + 1] = f2tf32(acc[nn][1] * SCALE_);
        }
        if (ok1) {
            g_qt[(size_t)a1 * HD_ + c]     = f2tf32(acc[nn][2] * SCALE_);
            g_qt[(size_t)a1 * HD_ + c + 1] = f2tf32(acc[nn][3] * SCALE_);
        }
    }
}

/* ------- fused flash attention: cp.async double-buffered tf32 mma ----------- */
#define QS_STRIDE 100
#define KS_STRIDE 100
#define VS_STRIDE 104
#define PS_STRIDE 68
#define ATTN_SMEM_WORDS (128*QS_STRIDE + 2*64*KS_STRIDE + 2*64*VS_STRIDE + 8*16*PS_STRIDE)

__global__ void __launch_bounds__(256, 1) attn_tc_kernel() {
    extern __shared__ uint32_t smu[];
    uint32_t* qs = smu;                                    /* [128][100]    */
    uint32_t* ks = qs + 128 * QS_STRIDE;                   /* [2][64][100]  */
    uint32_t* vs = ks + 2 * 64 * KS_STRIDE;                /* [2][64][104]  */
    uint32_t* ps = vs + 2 * 64 * VS_STRIDE;                /* [8][16][68]   */

    int it = blockIdx.x, bh = blockIdx.y;
    int b = bh >> 3, h = bh & 7;
    int i0 = it * 128;
    int tid  = threadIdx.x;
    int wid  = tid >> 5;
    int lane = tid & 31;
    int g    = lane >> 2;
    int tig  = lane & 3;
    uint32_t* pw = ps + wid * 16 * PS_STRIDE;

    uint32_t qs_s = (uint32_t)__cvta_generic_to_shared(qs);
    uint32_t ks_s = (uint32_t)__cvta_generic_to_shared(ks);
    uint32_t vs_s = (uint32_t)__cvta_generic_to_shared(vs);

    /* async Q fill: 128 rows x 24 16B-segs = 3072 ops */
    #pragma unroll
    for (int j = 0; j < 12; j++) {
        int item = tid + 256 * j;
        int r = item / 24, seg = item % 24;
        cp_async16(qs_s + (r * QS_STRIDE + seg * 4) * 4,
                   g_qt + ((size_t)(b * N_ + i0 + r) * H_ + h) * HD_ + seg * 4);
    }
    cp_commit();

    /* K/V tile fill into buffer bi: 64 rows x 24 segs x 2 tensors */
    auto fill_kv = [&](int bi, int jt) {
        int j0 = jt * 64;
        uint32_t kb = ks_s + bi * (64 * KS_STRIDE * 4);
        uint32_t vb = vs_s + bi * (64 * VS_STRIDE * 4);
        #pragma unroll
        for (int j = 0; j < 6; j++) {
            int item = tid + 256 * j;
            int r = item / 24, seg = item % 24;
            size_t src = (size_t)(b * N_ + j0 + r) * HD_ + seg * 4;
            cp_async16(kb + (r * KS_STRIDE + seg * 4) * 4, g_kt + src);
            cp_async16(vb + (r * VS_STRIDE + seg * 4) * 4, g_vt + src);
        }
        cp_commit();
    };
    fill_kv(0, 0);

    float m0 = -1e30f, m1 = -1e30f, l0 = 0.f, l1 = 0.f;
    float o_acc[12][4];
    #pragma unroll
    for (int nn = 0; nn < 12; nn++)
        #pragma unroll
        for (int r = 0; r < 4; r++) o_acc[nn][r] = 0.f;

    int row_a0 = wid * 16 + g;
    int row_a1 = wid * 16 + g + 8;

    for (int jt = 0; jt < 16; jt++) {
        cp_wait<0>();        /* Q (jt=0) + current K/V tile resident */
        __syncthreads();     /* also: all warps done reading the other buffer */
        if (jt < 15) fill_kv((jt + 1) & 1, jt + 1);   /* overlap with compute */
        uint32_t* ksb = ks + (jt & 1) * 64 * KS_STRIDE;
        uint32_t* vsb = vs + (jt & 1) * 64 * VS_STRIDE;

        float sv[8][4];
        #pragma unroll
        for (int nn = 0; nn < 8; nn++)
            #pragma unroll
            for (int r = 0; r < 4; r++) sv[nn][r] = 0.f;

        #pragma unroll
        for (int kk = 0; kk < 12; kk++) {
            uint32_t a[4];
            a[0] = qs[row_a0 * QS_STRIDE + kk * 8 + tig];
            a[1] = qs[row_a1 * QS_STRIDE + kk * 8 + tig];
            a[2] = qs[row_a0 * QS_STRIDE + kk * 8 + tig + 4];
            a[3] = qs[row_a1 * QS_STRIDE + kk * 8 + tig + 4];
            #pragma unroll
            for (int nn = 0; nn < 8; nn++) {
                uint32_t bb[2];
                bb[0] = ksb[(nn * 8 + g) * KS_STRIDE + kk * 8 + tig];
                bb[1] = ksb[(nn * 8 + g) * KS_STRIDE + kk * 8 + tig + 4];
                mma_tf32(sv[nn], a, bb);
            }
        }

        float rmax0 = -1e30f, rmax1 = -1e30f;
        #pragma unroll
        for (int nn = 0; nn < 8; nn++) {
            rmax0 = fmaxf(rmax0, fmaxf(sv[nn][0], sv[nn][1]));
            rmax1 = fmaxf(rmax1, fmaxf(sv[nn][2], sv[nn][3]));
        }
        #pragma unroll
        for (int o = 1; o <= 2; o <<= 1) {
            rmax0 = fmaxf(rmax0, __shfl_xor_sync(0xffffffffu, rmax0, o));
            rmax1 = fmaxf(rmax1, __shfl_xor_sync(0xffffffffu, rmax1, o));
        }
        float nm0 = fmaxf(m0, rmax0), nm1 = fmaxf(m1, rmax1);
        float corr0 = __expf(m0 - nm0), corr1 = __expf(m1 - nm1);
        float rs0 = 0.f, rs1 = 0.f;
        #pragma unroll
        for (int nn = 0; nn < 8; nn++) {
            float p00 = __expf(sv[nn][0] - nm0);
            float p01 = __expf(sv[nn][1] - nm0);
            float p10 = __expf(sv[nn][2] - nm1);
            float p11 = __expf(sv[nn][3] - nm1);
            rs0 += p00 + p01; rs1 += p10 + p11;
            int c = nn * 8 + tig * 2;
            pw[g * PS_STRIDE + c]           = f2tf32(p00);
            pw[g * PS_STRIDE + c + 1]       = f2tf32(p01);
            pw[(g + 8) * PS_STRIDE + c]     = f2tf32(p10);
            pw[(g + 8) * PS_STRIDE + c + 1] = f2tf32(p11);
        }
        #pragma unroll
        for (int o = 1; o <= 2; o <<= 1) {
            rs0 += __shfl_xor_sync(0xffffffffu, rs0, o);
            rs1 += __shfl_xor_sync(0xffffffffu, rs1, o);
        }
        l0 = l0 * corr0 + rs0;  m0 = nm0;
        l1 = l1 * corr1 + rs1;  m1 = nm1;
        #pragma unroll
        for (int nn = 0; nn < 12; nn++) {
            o_acc[nn][0] *= corr0; o_acc[nn][1] *= corr0;
            o_acc[nn][2] *= corr1; o_acc[nn][3] *= corr1;
        }
        __syncwarp();

        #pragma unroll
        for (int kk = 0; kk < 8; kk++) {
            uint32_t a[4];
            a[0] = pw[g * PS_STRIDE + kk * 8 + tig];
            a[1] = pw[(g + 8) * PS_STRIDE + kk * 8 + tig];
            a[2] = pw[g * PS_STRIDE + kk * 8 + tig + 4];
            a[3] = pw[(g + 8) * PS_STRIDE + kk * 8 + tig + 4];
            #pragma unroll
            for (int nn = 0; nn < 12; nn++) {
                uint32_t bb[2];
                bb[0] = vsb[(kk * 8 + tig) * VS_STRIDE + nn * 8 + g];
                bb[1] = vsb[(kk * 8 + tig + 4) * VS_STRIDE + nn * 8 + g];
                mma_tf32(o_acc[nn], a, bb);
            }
        }
        __syncwarp();
    }

    float inv0 = 1.f / l0, inv1 = 1.f / l1;
    int tok0 = b * N_ + i0 + row_a0;
    int tok1 = b * N_ + i0 + row_a1;
    #pragma unroll
    for (int nn = 0; nn < 12; nn++) {
        int c = nn * 8 + tig * 2;
        size_t o0 = ((size_t)tok0 * H_ + h) * HD_ + c;
        size_t o1 = ((size_t)tok1 * H_ + h) * HD_ + c;
        g_o[o0]     = o_acc[nn][0] * inv0;
        g_o[o0 + 1] = o_acc[nn][1] * inv0;
        g_o[o1]     = o_acc[nn][2] * inv1;
        g_o[o1 + 1] = o_acc[nn][3] * inv1;
    }
}

/* ------ grouped reduce, tf32 mma: out[t] += gate[a]*o[a] @ W2[e] (v2 red) --- */
#define RED_SMEM_WORDS (64*100 + 128*100)
__global__ void __launch_bounds__(256) red_tc_kernel(const float* __restrict__ W2,
                                                     float* __restrict__ out) {
    int e = blockIdx.y;
    int count = g_ecount[e];
    int base = blockIdx.x * 64;
    if (base >= count) return;

    extern __shared__ uint32_t rsm[];
    uint32_t* osT = rsm;
    uint32_t* w2T = rsm + 64 * 100;
    __shared__ int s_a[64];

    int tid = threadIdx.x;
    if (tid < 64) {
        int idx = base + tid; if (idx >= count) idx = count - 1;
        s_a[tid] = g_elist[e * NA + idx];
    }
    __syncthreads();

    for (int idx = tid; idx < 64 * 96; idx += 256) {
        int r = idx / 96, d = idx % 96;
        int a = s_a[r];
        osT[r * 100 + d] = f2tf32(g_gate[a] * g_o[(size_t)a * HD_ + d]);
    }

    int wid = tid >> 5, lane = tid & 31;
    int mg = wid & 3, ch = wid >> 2;
    int g = lane >> 2, tig = lane & 3;
    int row_a0 = mg * 16 + g, row_a1 = row_a0 + 8;
    const float* w2 = W2 + (size_t)e * HD_ * DIM_;

    bool ok0 = (base + row_a0 < count), ok1 = (base + row_a1 < count);
    int t0 = s_a[row_a0] >> 3, t1 = s_a[row_a1] >> 3;

    for (int ct = 0; ct < 6; ct++) {
        __syncthreads();
        for (int idx = tid; idx < 128 * 96; idx += 256) {
            int k = idx >> 7, c = idx & 127;
            w2T[c * 100 + k] = f2tf32(w2[(size_t)k * DIM_ + ct * 128 + c]);
        }
        __syncthreads();

        float acc[8][4];
        #pragma unroll
        for (int nn = 0; nn < 8; nn++)
            #pragma unroll
            for (int r = 0; r < 4; r++) acc[nn][r] = 0.f;

        #pragma unroll
        for (int kk = 0; kk < 12; kk++) {
            uint32_t a[4];
            a[0] = osT[row_a0 * 100 + kk * 8 + tig];
            a[1] = osT[row_a1 * 100 + kk * 8 + tig];
            a[2] = osT[row_a0 * 100 + kk * 8 + tig + 4];
            a[3] = osT[row_a1 * 100 + kk * 8 + tig + 4];
            #pragma unroll
            for (int nn = 0; nn < 8; nn++) {
                uint32_t bb[2];
                bb[0] = w2T[(ch * 64 + nn * 8 + g) * 100 + kk * 8 + tig];
                bb[1] = w2T[(ch * 64 + nn * 8 + g) * 100 + kk * 8 + tig + 4];
                mma_tf32(acc[nn], a, bb);
            }
        }

        #pragma unroll
        for (int nn = 0; nn < 8; nn++) {
            int c = ct * 128 + ch * 64 + nn * 8 + tig * 2;
            if (ok0) red_add_v2(&out[(size_t)t0 * DIM_ + c], acc[nn][0], acc[nn][1]);
            if (ok1) red_add_v2(&out[(size_t)t1 * DIM_ + c], acc[nn][2], acc[nn][3]);
        }
    }
}

/* ------------- aux loss + restore zeroed gating state for next run ---------- */
__global__ void aux_kernel(float* __restrict__ out, int out_size) {
    int tid = threadIdx.x;
    if (tid == 0) {
        float mesum = 0.f;
        for (int e = 0; e < E_; e++) mesum += g_me[e];
        float sw = 0.f;
        for (int e = 0; e < E_; e++)
            sw += (g_me[e] / mesum) * ((float)g_ecount[e] / (float)NA);
        sw *= (float)E_;
        float z = g_z / (float)NT;
        float aux = 0.1f * sw + 0.001f * z;
        if (out_size > NT * DIM_) out[out_size - 1] = aux;
    }
    __syncwarp();
    if (tid < E_) { g_me[tid] = 0.f; g_ecount[tid] = 0; }
    if (tid == 0) g_z = 0.f;
}

/* -------------------------------- launch ------------------------------------ */
extern "C" void kernel_launch(void* const* d_in, const int* in_sizes, int n_in,
                              void* d_out, int out_size) {
    const float* x    = (const float*)d_in[0];
    const float* Wg   = (const float*)d_in[1];
    const float* W1   = (const float*)d_in[2];
    const float* W2   = (const float*)d_in[3];
    const float* Wkv  = (const float*)d_in[4];
    const float* bkv  = (const float*)d_in[5];
    const int*   task = (const int*)d_in[6];
    float* out = (float*)d_out;

    cudaFuncSetAttribute(attn_tc_kernel,
                         cudaFuncAttributeMaxDynamicSharedMemorySize,
                         ATTN_SMEM_WORDS * (int)sizeof(uint32_t));
    cudaFuncSetAttribute(red_tc_kernel,
                         cudaFuncAttributeMaxDynamicSharedMemorySize,
                         RED_SMEM_WORDS * (int)sizeof(uint32_t));
    cudaFuncSetAttribute(q_tc_kernel,
                         cudaFuncAttributeMaxDynamicSharedMemorySize,
                         Q_SMEM_WORDS * (int)sizeof(uint32_t));

    gate_kernel<<<NT / 8, 256>>>(x, Wg, W1, task);                               /* #1 */
    kv_kernel<<<dim3(NT / 64, 3), 256>>>(x, Wkv, bkv);                           /* #2 */
    q_tc_kernel<<<dim3(512, E_), 256, Q_SMEM_WORDS * sizeof(uint32_t)>>>();      /* #3 */
    attn_tc_kernel<<<dim3(8, B_ * H_), 256,
                     ATTN_SMEM_WORDS * sizeof(uint32_t)>>>();                    /* #4 */
    zero_out_kernel<<<(out_size + 255) / 256, 256>>>(out, out_size);             /* #5 */
    red_tc_kernel<<<dim3(1024, E_), 256,
                    RED_SMEM_WORDS * sizeof(uint32_t)>>>(W2, out);               /* #6 */
    aux_kernel<<<1, 32>>>(out, out_size);                                        /* #7 */
}

// round 11
// speedup vs baseline: 1.4635x; 1.0439x over previous
#include <cuda_runtime.h>
#include <math.h>
#include <stdint.h>

#define B_    8
#define N_    1024
#define DIM_  768
#define H_    8
#define HD_   96
#define E_    24
#define NT    (B_*N_)      /* 8192 tokens */
#define NA    (NT*H_)      /* 65536 assignments */
#define SCALE_ 0.10206207261596575f  /* 96^-0.5 */

/* ------------------------- scratch (device globals) ------------------------- */
__device__ float    g_gate[NA];
__device__ float    g_me[E_];        /* zero-init; aux re-zeroes each run */
__device__ float    g_z;
__device__ int      g_ecount[E_];
__device__ int      g_elist[E_*NA];
__device__ uint32_t g_kt[NT*HD_];                 /* k as tf32 bits            */
__device__ uint32_t g_vt[NT*HD_];                 /* v as tf32 bits            */
__device__ uint32_t g_qt[(size_t)NA*HD_];         /* q*scale as tf32 bits      */
__device__ uint32_t g_ot[(size_t)NA*HD_];         /* gate*o as tf32 bits       */
__device__ uint32_t g_xt[(size_t)NT*DIM_];        /* x as tf32 bits            */
__device__ uint32_t g_w1t[(size_t)E_*HD_*DIM_];   /* W1^T [e][c][k], tf32 bits */
__device__ uint32_t g_w2t[(size_t)E_*DIM_*HD_];   /* W2^T [e][c][k], tf32 bits */

__device__ __forceinline__ uint32_t f2tf32(float f) {
    uint32_t r;
    asm("cvt.rna.tf32.f32 %0, %1;" : "=r"(r) : "f"(f));
    return r;
}

__device__ __forceinline__ void mma_tf32(float* d, const uint32_t* a, const uint32_t* b) {
    asm("mma.sync.aligned.m16n8k8.row.col.f32.tf32.tf32.f32 "
        "{%0,%1,%2,%3}, {%4,%5,%6,%7}, {%8,%9}, {%0,%1,%2,%3};"
        : "+f"(d[0]), "+f"(d[1]), "+f"(d[2]), "+f"(d[3])
        : "r"(a[0]), "r"(a[1]), "r"(a[2]), "r"(a[3]), "r"(b[0]), "r"(b[1]));
}

__device__ __forceinline__ void red_add_v2(float* addr, float a, float b) {
    asm volatile("red.global.add.v2.f32 [%0], {%1, %2};"
                 :: "l"(addr), "f"(a), "f"(b) : "memory");
}

__device__ __forceinline__ void cp_async16(uint32_t dst_smem, const void* src) {
    asm volatile("cp.async.cg.shared.global [%0], [%1], 16;"
                 :: "r"(dst_smem), "l"(src));
}
__device__ __forceinline__ void cp_commit() {
    asm volatile("cp.async.commit_group;");
}
template<int N> __device__ __forceinline__ void cp_wait() {
    asm volatile("cp.async.wait_group %0;" :: "n"(N));
}

/* ===== prep: gate+preconvert (blocks 0-1023) | kv (1024-1407) | zero (1408-1535) ===== */
__global__ void prep_kernel(const float* __restrict__ x,
                            const float* __restrict__ Wg,
                            const float* __restrict__ W1,
                            const float* __restrict__ W2,
                            const float* __restrict__ Wkv,
                            const float* __restrict__ bkv,
                            const int*   __restrict__ task_p,
                            float* __restrict__ out, int out_size) {
    __shared__ float sbuf[4352];          /* tile[32][33] (gate) / xsT+ws (kv) */
    __shared__ float sme[E_];
    __shared__ float szv;
    __shared__ int   scnt[E_];
    __shared__ int   sbase[E_];
    int bx  = blockIdx.x;
    int tid = threadIdx.x;

    if (bx < 1024) {
        /* ------------------- gating ------------------- */
        int warp = tid >> 5, lane = tid & 31;
        int t = bx * 8 + warp;
        if (tid < E_) { sme[tid] = 0.f; scnt[tid] = 0; }
        if (tid == 0) szv = 0.f;
        __syncthreads();

        int task = *task_p;
        const float* wg = Wg + (size_t)task * DIM_ * E_;
        const float* xr = x + (size_t)t * DIM_;

        float acc = 0.f;
        if (lane < E_) {
            #pragma unroll 4
            for (int d = 0; d < DIM_; d++) acc += xr[d] * wg[d * E_ + lane];
        }
        float logit = (lane < E_) ? acc : -1e30f;

        float m = logit;
        #pragma unroll
        for (int o = 16; o >= 1; o >>= 1) m = fmaxf(m, __shfl_xor_sync(0xffffffffu, m, o));
        float p = (lane < E_) ? expf(logit - m) : 0.f;
        float s = p;
        #pragma unroll
        for (int o = 16; o >= 1; o >>= 1) s += __shfl_xor_sync(0xffffffffu, s, o);
        float prob = p / s;
        float lse = m + logf(s);
        if (lane == 0) atomicAdd(&szv, lse * lse);
        if (lane < E_) atomicAdd(&sme[lane], prob);

        float val = (lane < E_) ? prob : -1.f;
        float sel_g = 0.f; int sel_e = 0;
        #pragma unroll
        for (int it = 0; it < H_; it++) {
            float mm = val;
            #pragma unroll
            for (int o = 16; o >= 1; o >>= 1)
                mm = fmaxf(mm, __shfl_xor_sync(0xffffffffu, mm, o));
            unsigned msk = __ballot_sync(0xffffffffu, val == mm);
            int src = __ffs(msk) - 1;
            if (lane == src) val = -1.f;
            if (lane == it) { sel_e = src; sel_g = mm; }
        }
        float gv = (lane < H_) ? sel_g : 0.f;
        #pragma unroll
        for (int o = 16; o >= 1; o >>= 1) gv += __shfl_xor_sync(0xffffffffu, gv, o);
        float denom = gv + 1e-6f;

        int pos = 0;
        if (lane < H_) pos = atomicAdd(&scnt[sel_e], 1);
        __syncthreads();
        if (tid < E_) sbase[tid] = atomicAdd(&g_ecount[tid], scnt[tid]);
        __syncthreads();
        if (lane < H_) {
            int a = t * H_ + lane;
            g_gate[a] = sel_g / denom;
            g_elist[sel_e * NA + sbase[sel_e] + pos] = a;
        }
        if (tid < E_) atomicAdd(&g_me[tid], sme[tid]);
        if (tid == 0) atomicAdd(&g_z, szv);

        /* ---- pre-convert x -> g_xt ---- */
        {
            const float4* xin = (const float4*)x;
            uint4* xout = (uint4*)g_xt;
            int base4 = bx * 1536;
            for (int i = tid; i < 1536; i += 256) {
                float4 v = xin[base4 + i];
                uint4 u;
                u.x = f2tf32(v.x); u.y = f2tf32(v.y);
                u.z = f2tf32(v.z); u.w = f2tf32(v.w);
                xout[base4 + i] = u;
            }
        }

        /* ---- W1 -> g_w1t [e][c][k] (1728 tiles) ---- */
        float (*tile)[33] = (float(*)[33])sbuf;
        int ty = tid >> 5, tx8 = tid & 31;
        for (int tix = bx; tix < 1728; tix += 1024) {
            int e  = tix / 72;
            int rem = tix % 72;
            int kt = rem / 3, ct = rem % 3;
            __syncthreads();
            for (int r = ty; r < 32; r += 8)
                tile[r][tx8] = W1[((size_t)e * DIM_ + kt * 32 + r) * HD_ + ct * 32 + tx8];
            __syncthreads();
            for (int r = ty; r < 32; r += 8)
                g_w1t[((size_t)e * HD_ + ct * 32 + r) * DIM_ + kt * 32 + tx8] =
                    f2tf32(tile[tx8][r]);
        }

        /* ---- W2 -> g_w2t [e][c][k] (1728 tiles; W2 is [e][96][768]) ---- */
        for (int tix = bx; tix < 1728; tix += 1024) {
            int e  = tix / 72;
            int rem = tix % 72;
            int kt = rem / 24, ct = rem % 24;      /* kt<3 over 96, ct<24 over 768 */
            __syncthreads();
            for (int r = ty; r < 32; r += 8)
                tile[r][tx8] = W2[((size_t)e * HD_ + kt * 32 + r) * DIM_ + ct * 32 + tx8];
            __syncthreads();
            for (int r = ty; r < 32; r += 8)
                g_w2t[((size_t)e * DIM_ + ct * 32 + r) * HD_ + kt * 32 + tx8] =
                    f2tf32(tile[tx8][r]);
        }
    } else if (bx < 1408) {
        /* ------------------- kv projection (SIMT) -> g_kt/g_vt ------------------- */
        float (*xsT)[68] = (float(*)[68])sbuf;
        float (*ws)[68]  = (float(*)[68])(sbuf + 32 * 68);
        int i = bx - 1024;
        int r0 = (i & 127) * 64;
        int c0 = (i >> 7) * 64;
        int ty = tid >> 4, tx = tid & 15;
        float acc[4][4] = {};

        for (int k0 = 0; k0 < DIM_; k0 += 32) {
            for (int ii = tid; ii < 64 * 32; ii += 256) {
                int r = ii >> 5, k = ii & 31;
                xsT[k][r] = x[(size_t)(r0 + r) * DIM_ + k0 + k];
            }
            for (int ii = tid; ii < 32 * 64; ii += 256) {
                int k = ii >> 6, c = ii & 63;
                ws[k][c] = Wkv[(size_t)(k0 + k) * (2 * HD_) + c0 + c];
            }
            __syncthreads();
            #pragma unroll
            for (int k = 0; k < 32; k++) {
                float4 a4 = *(const float4*)&xsT[k][ty * 4];
                float4 b4 = *(const float4*)&ws[k][tx * 4];
                float av[4] = {a4.x, a4.y, a4.z, a4.w};
                float bv[4] = {b4.x, b4.y, b4.z, b4.w};
                #pragma unroll
                for (int ri = 0; ri < 4; ri++)
                    #pragma unroll
                    for (int cj = 0; cj < 4; cj++) acc[ri][cj] += av[ri] * bv[cj];
            }
            __syncthreads();
        }
        #pragma unroll
        for (int ri = 0; ri < 4; ri++) {
            int r = r0 + ty * 4 + ri;
            #pragma unroll
            for (int cj = 0; cj < 4; cj++) {
                int c = c0 + tx * 4 + cj;
                uint32_t v = f2tf32(acc[ri][cj] + bkv[c]);
                if (c < HD_) g_kt[(size_t)r * HD_ + c]          = v;
                else         g_vt[(size_t)r * HD_ + (c - HD_)]  = v;
            }
        }
    } else {
        /* ------------------- zero output ------------------- */
        int zb = bx - 1408;
        float4* o4 = (float4*)out;
        const int n4 = NT * DIM_ / 4;
        for (int i = zb * 256 + tid; i < n4; i += 128 * 256)
            o4[i] = make_float4(0.f, 0.f, 0.f, 0.f);
        for (int i = NT * DIM_ + zb * 256 + tid; i < out_size; i += 128 * 256)
            out[i] = 0.f;
    }
}

/* ------- grouped q projection: cp.async double-buffered tf32 mma ------------ */
#define Q_SMEM_WORDS (2*128*36 + 2*96*36)
__global__ void __launch_bounds__(256) q_tc_kernel() {
    int e = blockIdx.y;
    int count = g_ecount[e];
    int base = blockIdx.x * 128;
    if (base >= count) return;

    extern __shared__ uint32_t qsm[];
    uint32_t* xs = qsm;
    uint32_t* ws = qsm + 2 * 128 * 36;
    __shared__ int s_a[128];
    int tid = threadIdx.x;
    if (tid < 128) {
        int idx = base + tid; if (idx >= count) idx = count - 1;
        s_a[tid] = g_elist[e * NA + idx];
    }
    __syncthreads();

    uint32_t xs_smem = (uint32_t)__cvta_generic_to_shared(xs);
    uint32_t ws_smem = (uint32_t)__cvta_generic_to_shared(ws);
    const uint32_t* w1t = g_w1t + (size_t)e * HD_ * DIM_;

    int wid = tid >> 5, lane = tid & 31;
    int g = lane >> 2, tig = lane & 3;
    int row_a0 = wid * 16 + g, row_a1 = row_a0 + 8;

    float acc[12][4];
    #pragma unroll
    for (int nn = 0; nn < 12; nn++)
        #pragma unroll
        for (int r = 0; r < 4; r++) acc[nn][r] = 0.f;

    auto fill = [&](int bi, int k0) {
        uint32_t xb = xs_smem + bi * (128 * 36 * 4);
        uint32_t wb = ws_smem + bi * (96 * 36 * 4);
        #pragma unroll
        for (int j = 0; j < 4; j++) {
            int item = tid + 256 * j;
            int r = item >> 3, seg = item & 7;
            int tok = s_a[r] >> 3;
            cp_async16(xb + (r * 36 + seg * 4) * 4,
                       g_xt + (size_t)tok * DIM_ + k0 + seg * 4);
        }
        #pragma unroll
        for (int j = 0; j < 3; j++) {
            int item = tid + 256 * j;
            int c = item >> 3, seg = item & 7;
            cp_async16(wb + (c * 36 + seg * 4) * 4,
                       w1t + (size_t)c * DIM_ + k0 + seg * 4);
        }
        cp_commit();
    };

    fill(0, 0);
    for (int c = 0; c < 24; c++) {
        if (c < 23) fill((c + 1) & 1, (c + 1) * 32);
        if (c < 23) cp_wait<1>(); else cp_wait<0>();
        __syncthreads();
        uint32_t* xsb = xs + (c & 1) * 128 * 36;
        uint32_t* wsb = ws + (c & 1) * 96 * 36;
        #pragma unroll
        for (int kk = 0; kk < 4; kk++) {
            uint32_t a[4];
            a[0] = xsb[row_a0 * 36 + kk * 8 + tig];
            a[1] = xsb[row_a1 * 36 + kk * 8 + tig];
            a[2] = xsb[row_a0 * 36 + kk * 8 + tig + 4];
            a[3] = xsb[row_a1 * 36 + kk * 8 + tig + 4];
            #pragma unroll
            for (int nn = 0; nn < 12; nn++) {
                uint32_t bb[2];
                bb[0] = wsb[(nn * 8 + g) * 36 + kk * 8 + tig];
                bb[1] = wsb[(nn * 8 + g) * 36 + kk * 8 + tig + 4];
                mma_tf32(acc[nn], a, bb);
            }
        }
        __syncthreads();
    }

    bool ok0 = (base + row_a0 < count), ok1 = (base + row_a1 < count);
    int a0 = s_a[row_a0], a1 = s_a[row_a1];
    #pragma unroll
    for (int nn = 0; nn < 12; nn++) {
        int c = nn * 8 + tig * 2;
        if (ok0) {
            g_qt[(size_t)a0 * HD_ + c]     = f2tf32(acc[nn][0] * SCALE_);
            g_qt[(size_t)a0 * HD_ + c + 1] = f2tf32(acc[nn][1] * SCALE_);
        }
        if (ok1) {
            g_qt[(size_t)a1 * HD_ + c]     = f2tf32(acc[nn][2] * SCALE_);
            g_qt[(size_t)a1 * HD_ + c + 1] = f2tf32(acc[nn][3] * SCALE_);
        }
    }
}

/* ------- fused flash attention: cp.async double-buffered tf32 mma ----------- */
#define QS_STRIDE 100
#define KS_STRIDE 100
#define VS_STRIDE 104
#define PS_STRIDE 68
#define ATTN_SMEM_WORDS (128*QS_STRIDE + 2*64*KS_STRIDE + 2*64*VS_STRIDE + 8*16*PS_STRIDE)

__global__ void __launch_bounds__(256, 1) attn_tc_kernel() {
    extern __shared__ uint32_t smu[];
    uint32_t* qs = smu;                                    /* [128][100]    */
    uint32_t* ks = qs + 128 * QS_STRIDE;                   /* [2][64][100]  */
    uint32_t* vs = ks + 2 * 64 * KS_STRIDE;                /* [2][64][104]  */
    uint32_t* ps = vs + 2 * 64 * VS_STRIDE;                /* [8][16][68]   */

    int it = blockIdx.x, bh = blockIdx.y;
    int b = bh >> 3, h = bh & 7;
    int i0 = it * 128;
    int tid  = threadIdx.x;
    int wid  = tid >> 5;
    int lane = tid & 31;
    int g    = lane >> 2;
    int tig  = lane & 3;
    uint32_t* pw = ps + wid * 16 * PS_STRIDE;

    uint32_t qs_s = (uint32_t)__cvta_generic_to_shared(qs);
    uint32_t ks_s = (uint32_t)__cvta_generic_to_shared(ks);
    uint32_t vs_s = (uint32_t)__cvta_generic_to_shared(vs);

    #pragma unroll
    for (int j = 0; j < 12; j++) {
        int item = tid + 256 * j;
        int r = item / 24, seg = item % 24;
        cp_async16(qs_s + (r * QS_STRIDE + seg * 4) * 4,
                   g_qt + ((size_t)(b * N_ + i0 + r) * H_ + h) * HD_ + seg * 4);
    }
    cp_commit();

    auto fill_kv = [&](int bi, int jt) {
        int j0 = jt * 64;
        uint32_t kb = ks_s + bi * (64 * KS_STRIDE * 4);
        uint32_t vb = vs_s + bi * (64 * VS_STRIDE * 4);
        #pragma unroll
        for (int j = 0; j < 6; j++) {
            int item = tid + 256 * j;
            int r = item / 24, seg = item % 24;
            size_t src = (size_t)(b * N_ + j0 + r) * HD_ + seg * 4;
            cp_async16(kb + (r * KS_STRIDE + seg * 4) * 4, g_kt + src);
            cp_async16(vb + (r * VS_STRIDE + seg * 4) * 4, g_vt + src);
        }
        cp_commit();
    };
    fill_kv(0, 0);

    float m0 = -1e30f, m1 = -1e30f, l0 = 0.f, l1 = 0.f;
    float o_acc[12][4];
    #pragma unroll
    for (int nn = 0; nn < 12; nn++)
        #pragma unroll
        for (int r = 0; r < 4; r++) o_acc[nn][r] = 0.f;

    int row_a0 = wid * 16 + g;
    int row_a1 = wid * 16 + g + 8;

    for (int jt = 0; jt < 16; jt++) {
        cp_wait<0>();
        __syncthreads();
        if (jt < 15) fill_kv((jt + 1) & 1, jt + 1);
        uint32_t* ksb = ks + (jt & 1) * 64 * KS_STRIDE;
        uint32_t* vsb = vs + (jt & 1) * 64 * VS_STRIDE;

        float sv[8][4];
        #pragma unroll
        for (int nn = 0; nn < 8; nn++)
            #pragma unroll
            for (int r = 0; r < 4; r++) sv[nn][r] = 0.f;

        #pragma unroll
        for (int kk = 0; kk < 12; kk++) {
            uint32_t a[4];
            a[0] = qs[row_a0 * QS_STRIDE + kk * 8 + tig];
            a[1] = qs[row_a1 * QS_STRIDE + kk * 8 + tig];
            a[2] = qs[row_a0 * QS_STRIDE + kk * 8 + tig + 4];
            a[3] = qs[row_a1 * QS_STRIDE + kk * 8 + tig + 4];
            #pragma unroll
            for (int nn = 0; nn < 8; nn++) {
                uint32_t bb[2];
                bb[0] = ksb[(nn * 8 + g) * KS_STRIDE + kk * 8 + tig];
                bb[1] = ksb[(nn * 8 + g) * KS_STRIDE + kk * 8 + tig + 4];
                mma_tf32(sv[nn], a, bb);
            }
        }

        float rmax0 = -1e30f, rmax1 = -1e30f;
        #pragma unroll
        for (int nn = 0; nn < 8; nn++) {
            rmax0 = fmaxf(rmax0, fmaxf(sv[nn][0], sv[nn][1]));
            rmax1 = fmaxf(rmax1, fmaxf(sv[nn][2], sv[nn][3]));
        }
        #pragma unroll
        for (int o = 1; o <= 2; o <<= 1) {
            rmax0 = fmaxf(rmax0, __shfl_xor_sync(0xffffffffu, rmax0, o));
            rmax1 = fmaxf(rmax1, __shfl_xor_sync(0xffffffffu, rmax1, o));
        }
        float nm0 = fmaxf(m0, rmax0), nm1 = fmaxf(m1, rmax1);
        float corr0 = __expf(m0 - nm0), corr1 = __expf(m1 - nm1);
        float rs0 = 0.f, rs1 = 0.f;
        #pragma unroll
        for (int nn = 0; nn < 8; nn++) {
            float p00 = __expf(sv[nn][0] - nm0);
            float p01 = __expf(sv[nn][1] - nm0);
            float p10 = __expf(sv[nn][2] - nm1);
            float p11 = __expf(sv[nn][3] - nm1);
            rs0 += p00 + p01; rs1 += p10 + p11;
            int c = nn * 8 + tig * 2;
            pw[g * PS_STRIDE + c]           = f2tf32(p00);
            pw[g * PS_STRIDE + c + 1]       = f2tf32(p01);
            pw[(g + 8) * PS_STRIDE + c]     = f2tf32(p10);
            pw[(g + 8) * PS_STRIDE + c + 1] = f2tf32(p11);
        }
        #pragma unroll
        for (int o = 1; o <= 2; o <<= 1) {
            rs0 += __shfl_xor_sync(0xffffffffu, rs0, o);
            rs1 += __shfl_xor_sync(0xffffffffu, rs1, o);
        }
        l0 = l0 * corr0 + rs0;  m0 = nm0;
        l1 = l1 * corr1 + rs1;  m1 = nm1;
        #pragma unroll
        for (int nn = 0; nn < 12; nn++) {
            o_acc[nn][0] *= corr0; o_acc[nn][1] *= corr0;
            o_acc[nn][2] *= corr1; o_acc[nn][3] *= corr1;
        }
        __syncwarp();

        #pragma unroll
        for (int kk = 0; kk < 8; kk++) {
            uint32_t a[4];
            a[0] = pw[g * PS_STRIDE + kk * 8 + tig];
            a[1] = pw[(g + 8) * PS_STRIDE + kk * 8 + tig];
            a[2] = pw[g * PS_STRIDE + kk * 8 + tig + 4];
            a[3] = pw[(g + 8) * PS_STRIDE + kk * 8 + tig + 4];
            #pragma unroll
            for (int nn = 0; nn < 12; nn++) {
                uint32_t bb[2];
                bb[0] = vsb[(kk * 8 + tig) * VS_STRIDE + nn * 8 + g];
                bb[1] = vsb[(kk * 8 + tig + 4) * VS_STRIDE + nn * 8 + g];
                mma_tf32(o_acc[nn], a, bb);
            }
        }
        __syncwarp();
    }

    /* epilogue: write gate-weighted tf32 o rows (same fp32 op order as before) */
    float inv0 = 1.f / l0, inv1 = 1.f / l1;
    int tok0 = b * N_ + i0 + row_a0;
    int tok1 = b * N_ + i0 + row_a1;
    int a0 = tok0 * H_ + h, a1 = tok1 * H_ + h;
    float ga0 = g_gate[a0], ga1 = g_gate[a1];
    #pragma unroll
    for (int nn = 0; nn < 12; nn++) {
        int c = nn * 8 + tig * 2;
        g_ot[(size_t)a0 * HD_ + c]     = f2tf32(ga0 * (o_acc[nn][0] * inv0));
        g_ot[(size_t)a0 * HD_ + c + 1] = f2tf32(ga0 * (o_acc[nn][1] * inv0));
        g_ot[(size_t)a1 * HD_ + c]     = f2tf32(ga1 * (o_acc[nn][2] * inv1));
        g_ot[(size_t)a1 * HD_ + c + 1] = f2tf32(ga1 * (o_acc[nn][3] * inv1));
    }
}

/* -- grouped reduce: cp.async double-buffered tf32 mma, v2-red epilogue ------ */
/* 64 assignments x 8 col-chunks of 96; warps 4 row-grp x 2 col-grp            */
#define RED_SMEM_WORDS (64*100 + 2*96*100)   /* 102400 bytes */
__global__ void __launch_bounds__(256) red_tc_kernel(float* __restrict__ out) {
    int e = blockIdx.y;
    int count = g_ecount[e];
    int base = blockIdx.x * 64;
    if (base >= count) return;

    extern __shared__ uint32_t rsm[];
    uint32_t* osT = rsm;                      /* [64][100]    */
    uint32_t* w2T = rsm + 64 * 100;           /* [2][96][100] */
    __shared__ int s_a[64];

    int tid = threadIdx.x;
    if (tid < 64) {
        int idx = base + tid; if (idx >= count) idx = count - 1;
        s_a[tid] = g_elist[e * NA + idx];
    }
    __syncthreads();

    uint32_t osT_s = (uint32_t)__cvta_generic_to_shared(osT);
    uint32_t w2T_s = (uint32_t)__cvta_generic_to_shared(w2T);
    const uint32_t* w2te = g_w2t + (size_t)e * DIM_ * HD_;

    /* osT fill: 64 rows x 24 segs (gathered) */
    #pragma unroll
    for (int j = 0; j < 6; j++) {
        int item = tid + 256 * j;
        int r = item / 24, seg = item % 24;
        int a = s_a[r];
        cp_async16(osT_s + (r * 100 + seg * 4) * 4,
                   g_ot + (size_t)a * HD_ + seg * 4);
    }

    auto fill_w2 = [&](int bi, int ct) {
        uint32_t wb = w2T_s + bi * (96 * 100 * 4);
        const uint32_t* src = w2te + (size_t)(ct * 96) * HD_;
        #pragma unroll
        for (int j = 0; j < 9; j++) {
            int item = tid + 256 * j;
            int c = item / 24, seg = item % 24;
            cp_async16(wb + (c * 100 + seg * 4) * 4,
                       src + (size_t)c * HD_ + seg * 4);
        }
        cp_commit();   /* first call also commits the osT ops above */
    };
    fill_w2(0, 0);

    int wid = tid >> 5, lane = tid & 31;
    int mg = wid & 3, ch = wid >> 2;
    int g = lane >> 2, tig = lane & 3;
    int row_a0 = mg * 16 + g, row_a1 = row_a0 + 8;
    bool ok0 = (base + row_a0 < count), ok1 = (base + row_a1 < count);
    int t0 = s_a[row_a0] >> 3, t1 = s_a[row_a1] >> 3;

    for (int ct = 0; ct < 8; ct++) {
        if (ct < 7) fill_w2((ct + 1) & 1, ct + 1);
        if (ct < 7) cp_wait<1>(); else cp_wait<0>();
        __syncthreads();
        uint32_t* wsb = w2T + (ct & 1) * 96 * 100;

        float acc[6][4];
        #pragma unroll
        for (int nn = 0; nn < 6; nn++)
            #pragma unroll
            for (int r = 0; r < 4; r++) acc[nn][r] = 0.f;

        #pragma unroll
        for (int kk = 0; kk < 12; kk++) {
            uint32_t a[4];
            a[0] = osT[row_a0 * 100 + kk * 8 + tig];
            a[1] = osT[row_a1 * 100 + kk * 8 + tig];
            a[2] = osT[row_a0 * 100 + kk * 8 + tig + 4];
            a[3] = osT[row_a1 * 100 + kk * 8 + tig + 4];
            #pragma unroll
            for (int nn = 0; nn < 6; nn++) {
                uint32_t bb[2];
                bb[0] = wsb[(ch * 48 + nn * 8 + g) * 100 + kk * 8 + tig];
                bb[1] = wsb[(ch * 48 + nn * 8 + g) * 100 + kk * 8 + tig + 4];
                mma_tf32(acc[nn], a, bb);
            }
        }

        #pragma unroll
        for (int nn = 0; nn < 6; nn++) {
            int c = ct * 96 + ch * 48 + nn * 8 + tig * 2;
            if (ok0) red_add_v2(&out[(size_t)t0 * DIM_ + c], acc[nn][0], acc[nn][1]);
            if (ok1) red_add_v2(&out[(size_t)t1 * DIM_ + c], acc[nn][2], acc[nn][3]);
        }
        __syncthreads();
    }
}

/* ------------- aux loss + restore zeroed gating state for next run ---------- */
__global__ void aux_kernel(float* __restrict__ out, int out_size) {
    int tid = threadIdx.x;
    if (tid == 0) {
        float mesum = 0.f;
        for (int e = 0; e < E_; e++) mesum += g_me[e];
        float sw = 0.f;
        for (int e = 0; e < E_; e++)
            sw += (g_me[e] / mesum) * ((float)g_ecount[e] / (float)NA);
        sw *= (float)E_;
        float z = g_z / (float)NT;
        float aux = 0.1f * sw + 0.001f * z;
        if (out_size > NT * DIM_) out[out_size - 1] = aux;
    }
    __syncwarp();
    if (tid < E_) { g_me[tid] = 0.f; g_ecount[tid] = 0; }
    if (tid == 0) g_z = 0.f;
}

/* -------------------------------- launch ------------------------------------ */
extern "C" void kernel_launch(void* const* d_in, const int* in_sizes, int n_in,
                              void* d_out, int out_size) {
    const float* x    = (const float*)d_in[0];
    const float* Wg   = (const float*)d_in[1];
    const float* W1   = (const float*)d_in[2];
    const float* W2   = (const float*)d_in[3];
    const float* Wkv  = (const float*)d_in[4];
    const float* bkv  = (const float*)d_in[5];
    const int*   task = (const int*)d_in[6];
    float* out = (float*)d_out;

    cudaFuncSetAttribute(attn_tc_kernel,
                         cudaFuncAttributeMaxDynamicSharedMemorySize,
                         ATTN_SMEM_WORDS * (int)sizeof(uint32_t));
    cudaFuncSetAttribute(red_tc_kernel,
                         cudaFuncAttributeMaxDynamicSharedMemorySize,
                         RED_SMEM_WORDS * (int)sizeof(uint32_t));
    cudaFuncSetAttribute(q_tc_kernel,
                         cudaFuncAttributeMaxDynamicSharedMemorySize,
                         Q_SMEM_WORDS * (int)sizeof(uint32_t));

    prep_kernel<<<1536, 256>>>(x, Wg, W1, W2, Wkv, bkv, task, out, out_size); /* #1 */
    q_tc_kernel<<<dim3(512, E_), 256, Q_SMEM_WORDS * sizeof(uint32_t)>>>();  /* #2 */
    attn_tc_kernel<<<dim3(8, B_ * H_), 256,
                     ATTN_SMEM_WORDS * sizeof(uint32_t)>>>();                /* #3 */
    red_tc_kernel<<<dim3(1024, E_), 256,
                    RED_SMEM_WORDS * sizeof(uint32_t)>>>(out);               /* #4 */
    aux_kernel<<<1, 32>>>(out, out_size);                                    /* #5 */
}

// round 12
// speedup vs baseline: 1.5606x; 1.0664x over previous
#include <cuda_runtime.h>
#include <math.h>
#include <stdint.h>

#define B_    8
#define N_    1024
#define DIM_  768
#define H_    8
#define HD_   96
#define E_    24
#define NT    (B_*N_)      /* 8192 tokens */
#define NA    (NT*H_)      /* 65536 assignments */
#define SCALE_ 0.10206207261596575f  /* 96^-0.5 */

/* ------------------------- scratch (device globals) ------------------------- */
__device__ float    g_gate[NA];
__device__ float    g_me[E_];        /* zero-init; aux re-zeroes each run */
__device__ float    g_z;
__device__ int      g_ecount[E_];
__device__ int      g_elist[E_*NA];
__device__ uint32_t g_kt[NT*HD_];                 /* k as tf32 bits            */
__device__ uint32_t g_vt[NT*HD_];                 /* v as tf32 bits            */
__device__ uint32_t g_qt[(size_t)NA*HD_];         /* q*scale as tf32 bits      */
__device__ uint32_t g_ot[(size_t)NA*HD_];         /* gate*o as tf32 bits       */
__device__ uint32_t g_xt[(size_t)NT*DIM_];        /* x as tf32 bits            */
__device__ uint32_t g_w1t[(size_t)E_*HD_*DIM_];   /* W1^T [e][c][k], tf32 bits */
__device__ uint32_t g_w2t[(size_t)E_*DIM_*HD_];   /* W2^T [e][c][k], tf32 bits */

__device__ __forceinline__ uint32_t f2tf32(float f) {
    uint32_t r;
    asm("cvt.rna.tf32.f32 %0, %1;" : "=r"(r) : "f"(f));
    return r;
}

__device__ __forceinline__ void mma_tf32(float* d, const uint32_t* a, const uint32_t* b) {
    asm("mma.sync.aligned.m16n8k8.row.col.f32.tf32.tf32.f32 "
        "{%0,%1,%2,%3}, {%4,%5,%6,%7}, {%8,%9}, {%0,%1,%2,%3};"
        : "+f"(d[0]), "+f"(d[1]), "+f"(d[2]), "+f"(d[3])
        : "r"(a[0]), "r"(a[1]), "r"(a[2]), "r"(a[3]), "r"(b[0]), "r"(b[1]));
}

__device__ __forceinline__ void red_add_v2(float* addr, float a, float b) {
    asm volatile("red.global.add.v2.f32 [%0], {%1, %2};"
                 :: "l"(addr), "f"(a), "f"(b) : "memory");
}

__device__ __forceinline__ void cp_async16(uint32_t dst_smem, const void* src) {
    asm volatile("cp.async.cg.shared.global [%0], [%1], 16;"
                 :: "r"(dst_smem), "l"(src));
}
__device__ __forceinline__ void cp_commit() {
    asm volatile("cp.async.commit_group;");
}
template<int N> __device__ __forceinline__ void cp_wait() {
    asm volatile("cp.async.wait_group %0;" :: "n"(N));
}

/* ===== prep: gate+preconvert (blocks 0-1023) | kv (1024-1407) | zero (1408-1535) ===== */
__global__ void prep_kernel(const float* __restrict__ x,
                            const float* __restrict__ Wg,
                            const float* __restrict__ W1,
                            const float* __restrict__ W2,
                            const float* __restrict__ Wkv,
                            const float* __restrict__ bkv,
                            const int*   __restrict__ task_p,
                            float* __restrict__ out, int out_size) {
    __shared__ float sbuf[4352];
    __shared__ float sme[E_];
    __shared__ float szv;
    __shared__ int   scnt[E_];
    __shared__ int   sbase[E_];
    int bx  = blockIdx.x;
    int tid = threadIdx.x;

    if (bx < 1024) {
        /* ------------------- gating ------------------- */
        int warp = tid >> 5, lane = tid & 31;
        int t = bx * 8 + warp;
        if (tid < E_) { sme[tid] = 0.f; scnt[tid] = 0; }
        if (tid == 0) szv = 0.f;
        __syncthreads();

        int task = *task_p;
        const float* wg = Wg + (size_t)task * DIM_ * E_;
        const float* xr = x + (size_t)t * DIM_;

        float acc = 0.f;
        if (lane < E_) {
            #pragma unroll 4
            for (int d = 0; d < DIM_; d++) acc += xr[d] * wg[d * E_ + lane];
        }
        float logit = (lane < E_) ? acc : -1e30f;

        float m = logit;
        #pragma unroll
        for (int o = 16; o >= 1; o >>= 1) m = fmaxf(m, __shfl_xor_sync(0xffffffffu, m, o));
        float p = (lane < E_) ? expf(logit - m) : 0.f;
        float s = p;
        #pragma unroll
        for (int o = 16; o >= 1; o >>= 1) s += __shfl_xor_sync(0xffffffffu, s, o);
        float prob = p / s;
        float lse = m + logf(s);
        if (lane == 0) atomicAdd(&szv, lse * lse);
        if (lane < E_) atomicAdd(&sme[lane], prob);

        float val = (lane < E_) ? prob : -1.f;
        float sel_g = 0.f; int sel_e = 0;
        #pragma unroll
        for (int it = 0; it < H_; it++) {
            float mm = val;
            #pragma unroll
            for (int o = 16; o >= 1; o >>= 1)
                mm = fmaxf(mm, __shfl_xor_sync(0xffffffffu, mm, o));
            unsigned msk = __ballot_sync(0xffffffffu, val == mm);
            int src = __ffs(msk) - 1;
            if (lane == src) val = -1.f;
            if (lane == it) { sel_e = src; sel_g = mm; }
        }
        float gv = (lane < H_) ? sel_g : 0.f;
        #pragma unroll
        for (int o = 16; o >= 1; o >>= 1) gv += __shfl_xor_sync(0xffffffffu, gv, o);
        float denom = gv + 1e-6f;

        int pos = 0;
        if (lane < H_) pos = atomicAdd(&scnt[sel_e], 1);
        __syncthreads();
        if (tid < E_) sbase[tid] = atomicAdd(&g_ecount[tid], scnt[tid]);
        __syncthreads();
        if (lane < H_) {
            int a = t * H_ + lane;
            g_gate[a] = sel_g / denom;
            g_elist[sel_e * NA + sbase[sel_e] + pos] = a;
        }
        if (tid < E_) atomicAdd(&g_me[tid], sme[tid]);
        if (tid == 0) atomicAdd(&g_z, szv);

        /* ---- pre-convert x -> g_xt ---- */
        {
            const float4* xin = (const float4*)x;
            uint4* xout = (uint4*)g_xt;
            int base4 = bx * 1536;
            for (int i = tid; i < 1536; i += 256) {
                float4 v = xin[base4 + i];
                uint4 u;
                u.x = f2tf32(v.x); u.y = f2tf32(v.y);
                u.z = f2tf32(v.z); u.w = f2tf32(v.w);
                xout[base4 + i] = u;
            }
        }

        /* ---- W1 -> g_w1t [e][c][k] (1728 tiles) ---- */
        float (*tile)[33] = (float(*)[33])sbuf;
        int ty = tid >> 5, tx8 = tid & 31;
        for (int tix = bx; tix < 1728; tix += 1024) {
            int e  = tix / 72;
            int rem = tix % 72;
            int kt = rem / 3, ct = rem % 3;
            __syncthreads();
            for (int r = ty; r < 32; r += 8)
                tile[r][tx8] = W1[((size_t)e * DIM_ + kt * 32 + r) * HD_ + ct * 32 + tx8];
            __syncthreads();
            for (int r = ty; r < 32; r += 8)
                g_w1t[((size_t)e * HD_ + ct * 32 + r) * DIM_ + kt * 32 + tx8] =
                    f2tf32(tile[tx8][r]);
        }

        /* ---- W2 -> g_w2t [e][c][k] (1728 tiles; W2 is [e][96][768]) ---- */
        for (int tix = bx; tix < 1728; tix += 1024) {
            int e  = tix / 72;
            int rem = tix % 72;
            int kt = rem / 24, ct = rem % 24;
            __syncthreads();
            for (int r = ty; r < 32; r += 8)
                tile[r][tx8] = W2[((size_t)e * HD_ + kt * 32 + r) * DIM_ + ct * 32 + tx8];
            __syncthreads();
            for (int r = ty; r < 32; r += 8)
                g_w2t[((size_t)e * DIM_ + ct * 32 + r) * HD_ + kt * 32 + tx8] =
                    f2tf32(tile[tx8][r]);
        }
    } else if (bx < 1408) {
        /* ------------------- kv projection (SIMT) -> g_kt/g_vt ------------------- */
        float (*xsT)[68] = (float(*)[68])sbuf;
        float (*ws)[68]  = (float(*)[68])(sbuf + 32 * 68);
        int i = bx - 1024;
        int r0 = (i & 127) * 64;
        int c0 = (i >> 7) * 64;
        int ty = tid >> 4, tx = tid & 15;
        float acc[4][4] = {};

        for (int k0 = 0; k0 < DIM_; k0 += 32) {
            for (int ii = tid; ii < 64 * 32; ii += 256) {
                int r = ii >> 5, k = ii & 31;
                xsT[k][r] = x[(size_t)(r0 + r) * DIM_ + k0 + k];
            }
            for (int ii = tid; ii < 32 * 64; ii += 256) {
                int k = ii >> 6, c = ii & 63;
                ws[k][c] = Wkv[(size_t)(k0 + k) * (2 * HD_) + c0 + c];
            }
            __syncthreads();
            #pragma unroll
            for (int k = 0; k < 32; k++) {
                float4 a4 = *(const float4*)&xsT[k][ty * 4];
                float4 b4 = *(const float4*)&ws[k][tx * 4];
                float av[4] = {a4.x, a4.y, a4.z, a4.w};
                float bv[4] = {b4.x, b4.y, b4.z, b4.w};
                #pragma unroll
                for (int ri = 0; ri < 4; ri++)
                    #pragma unroll
                    for (int cj = 0; cj < 4; cj++) acc[ri][cj] += av[ri] * bv[cj];
            }
            __syncthreads();
        }
        #pragma unroll
        for (int ri = 0; ri < 4; ri++) {
            int r = r0 + ty * 4 + ri;
            #pragma unroll
            for (int cj = 0; cj < 4; cj++) {
                int c = c0 + tx * 4 + cj;
                uint32_t v = f2tf32(acc[ri][cj] + bkv[c]);
                if (c < HD_) g_kt[(size_t)r * HD_ + c]          = v;
                else         g_vt[(size_t)r * HD_ + (c - HD_)]  = v;
            }
        }
    } else {
        /* ------------------- zero output ------------------- */
        int zb = bx - 1408;
        float4* o4 = (float4*)out;
        const int n4 = NT * DIM_ / 4;
        for (int i = zb * 256 + tid; i < n4; i += 128 * 256)
            o4[i] = make_float4(0.f, 0.f, 0.f, 0.f);
        for (int i = NT * DIM_ + zb * 256 + tid; i < out_size; i += 128 * 256)
            out[i] = 0.f;
    }
}

/* ------- grouped q projection: cp.async double-buffered tf32 mma ------------ */
#define Q_SMEM_WORDS (2*128*36 + 2*96*36)
__global__ void __launch_bounds__(256) q_tc_kernel() {
    int e = blockIdx.y;
    int count = g_ecount[e];
    int base = blockIdx.x * 128;
    if (base >= count) return;

    extern __shared__ uint32_t qsm[];
    uint32_t* xs = qsm;
    uint32_t* ws = qsm + 2 * 128 * 36;
    __shared__ int s_a[128];
    int tid = threadIdx.x;
    if (tid < 128) {
        int idx = base + tid; if (idx >= count) idx = count - 1;
        s_a[tid] = g_elist[e * NA + idx];
    }
    __syncthreads();

    uint32_t xs_smem = (uint32_t)__cvta_generic_to_shared(xs);
    uint32_t ws_smem = (uint32_t)__cvta_generic_to_shared(ws);
    const uint32_t* w1t = g_w1t + (size_t)e * HD_ * DIM_;

    int wid = tid >> 5, lane = tid & 31;
    int g = lane >> 2, tig = lane & 3;
    int row_a0 = wid * 16 + g, row_a1 = row_a0 + 8;

    float acc[12][4];
    #pragma unroll
    for (int nn = 0; nn < 12; nn++)
        #pragma unroll
        for (int r = 0; r < 4; r++) acc[nn][r] = 0.f;

    auto fill = [&](int bi, int k0) {
        uint32_t xb = xs_smem + bi * (128 * 36 * 4);
        uint32_t wb = ws_smem + bi * (96 * 36 * 4);
        #pragma unroll
        for (int j = 0; j < 4; j++) {
            int item = tid + 256 * j;
            int r = item >> 3, seg = item & 7;
            int tok = s_a[r] >> 3;
            cp_async16(xb + (r * 36 + seg * 4) * 4,
                       g_xt + (size_t)tok * DIM_ + k0 + seg * 4);
        }
        #pragma unroll
        for (int j = 0; j < 3; j++) {
            int item = tid + 256 * j;
            int c = item >> 3, seg = item & 7;
            cp_async16(wb + (c * 36 + seg * 4) * 4,
                       w1t + (size_t)c * DIM_ + k0 + seg * 4);
        }
        cp_commit();
    };

    fill(0, 0);
    for (int c = 0; c < 24; c++) {
        if (c < 23) fill((c + 1) & 1, (c + 1) * 32);
        if (c < 23) cp_wait<1>(); else cp_wait<0>();
        __syncthreads();
        uint32_t* xsb = xs + (c & 1) * 128 * 36;
        uint32_t* wsb = ws + (c & 1) * 96 * 36;
        #pragma unroll
        for (int kk = 0; kk < 4; kk++) {
            uint32_t a[4];
            a[0] = xsb[row_a0 * 36 + kk * 8 + tig];
            a[1] = xsb[row_a1 * 36 + kk * 8 + tig];
            a[2] = xsb[row_a0 * 36 + kk * 8 + tig + 4];
            a[3] = xsb[row_a1 * 36 + kk * 8 + tig + 4];
            #pragma unroll
            for (int nn = 0; nn < 12; nn++) {
                uint32_t bb[2];
                bb[0] = wsb[(nn * 8 + g) * 36 + kk * 8 + tig];
                bb[1] = wsb[(nn * 8 + g) * 36 + kk * 8 + tig + 4];
                mma_tf32(acc[nn], a, bb);
            }
        }
        __syncthreads();
    }

    bool ok0 = (base + row_a0 < count), ok1 = (base + row_a1 < count);
    int a0 = s_a[row_a0], a1 = s_a[row_a1];
    #pragma unroll
    for (int nn = 0; nn < 12; nn++) {
        int c = nn * 8 + tig * 2;
        if (ok0) {
            g_qt[(size_t)a0 * HD_ + c]     = f2tf32(acc[nn][0] * SCALE_);
            g_qt[(size_t)a0 * HD_ + c + 1] = f2tf32(acc[nn][1] * SCALE_);
        }
        if (ok1) {
            g_qt[(size_t)a1 * HD_ + c]     = f2tf32(acc[nn][2] * SCALE_);
            g_qt[(size_t)a1 * HD_ + c + 1] = f2tf32(acc[nn][3] * SCALE_);
        }
    }
}

/* ------- fused flash attention: cp.async double-buffered tf32 mma ----------- */
#define QS_STRIDE 100
#define KS_STRIDE 100
#define VS_STRIDE 104
#define PS_STRIDE 68
#define ATTN_SMEM_WORDS (128*QS_STRIDE + 2*64*KS_STRIDE + 2*64*VS_STRIDE + 8*16*PS_STRIDE)

__global__ void __launch_bounds__(256, 1) attn_tc_kernel() {
    extern __shared__ uint32_t smu[];
    uint32_t* qs = smu;                                    /* [128][100]    */
    uint32_t* ks = qs + 128 * QS_STRIDE;                   /* [2][64][100]  */
    uint32_t* vs = ks + 2 * 64 * KS_STRIDE;                /* [2][64][104]  */
    uint32_t* ps = vs + 2 * 64 * VS_STRIDE;                /* [8][16][68]   */

    int it = blockIdx.x, bh = blockIdx.y;
    int b = bh >> 3, h = bh & 7;
    int i0 = it * 128;
    int tid  = threadIdx.x;
    int wid  = tid >> 5;
    int lane = tid & 31;
    int g    = lane >> 2;
    int tig  = lane & 3;
    uint32_t* pw = ps + wid * 16 * PS_STRIDE;

    uint32_t qs_s = (uint32_t)__cvta_generic_to_shared(qs);
    uint32_t ks_s = (uint32_t)__cvta_generic_to_shared(ks);
    uint32_t vs_s = (uint32_t)__cvta_generic_to_shared(vs);

    #pragma unroll
    for (int j = 0; j < 12; j++) {
        int item = tid + 256 * j;
        int r = item / 24, seg = item % 24;
        cp_async16(qs_s + (r * QS_STRIDE + seg * 4) * 4,
                   g_qt + ((size_t)(b * N_ + i0 + r) * H_ + h) * HD_ + seg * 4);
    }
    cp_commit();

    auto fill_kv = [&](int bi, int jt) {
        int j0 = jt * 64;
        uint32_t kb = ks_s + bi * (64 * KS_STRIDE * 4);
        uint32_t vb = vs_s + bi * (64 * VS_STRIDE * 4);
        #pragma unroll
        for (int j = 0; j < 6; j++) {
            int item = tid + 256 * j;
            int r = item / 24, seg = item % 24;
            size_t src = (size_t)(b * N_ + j0 + r) * HD_ + seg * 4;
            cp_async16(kb + (r * KS_STRIDE + seg * 4) * 4, g_kt + src);
            cp_async16(vb + (r * VS_STRIDE + seg * 4) * 4, g_vt + src);
        }
        cp_commit();
    };
    fill_kv(0, 0);

    float m0 = -1e30f, m1 = -1e30f, l0 = 0.f, l1 = 0.f;
    float o_acc[12][4];
    #pragma unroll
    for (int nn = 0; nn < 12; nn++)
        #pragma unroll
        for (int r = 0; r < 4; r++) o_acc[nn][r] = 0.f;

    int row_a0 = wid * 16 + g;
    int row_a1 = wid * 16 + g + 8;

    for (int jt = 0; jt < 16; jt++) {
        cp_wait<0>();
        __syncthreads();
        if (jt < 15) fill_kv((jt + 1) & 1, jt + 1);
        uint32_t* ksb = ks + (jt & 1) * 64 * KS_STRIDE;
        uint32_t* vsb = vs + (jt & 1) * 64 * VS_STRIDE;

        float sv[8][4];
        #pragma unroll
        for (int nn = 0; nn < 8; nn++)
            #pragma unroll
            for (int r = 0; r < 4; r++) sv[nn][r] = 0.f;

        #pragma unroll
        for (int kk = 0; kk < 12; kk++) {
            uint32_t a[4];
            a[0] = qs[row_a0 * QS_STRIDE + kk * 8 + tig];
            a[1] = qs[row_a1 * QS_STRIDE + kk * 8 + tig];
            a[2] = qs[row_a0 * QS_STRIDE + kk * 8 + tig + 4];
            a[3] = qs[row_a1 * QS_STRIDE + kk * 8 + tig + 4];
            #pragma unroll
            for (int nn = 0; nn < 8; nn++) {
                uint32_t bb[2];
                bb[0] = ksb[(nn * 8 + g) * KS_STRIDE + kk * 8 + tig];
                bb[1] = ksb[(nn * 8 + g) * KS_STRIDE + kk * 8 + tig + 4];
                mma_tf32(sv[nn], a, bb);
            }
        }

        float rmax0 = -1e30f, rmax1 = -1e30f;
        #pragma unroll
        for (int nn = 0; nn < 8; nn++) {
            rmax0 = fmaxf(rmax0, fmaxf(sv[nn][0], sv[nn][1]));
            rmax1 = fmaxf(rmax1, fmaxf(sv[nn][2], sv[nn][3]));
        }
        #pragma unroll
        for (int o = 1; o <= 2; o <<= 1) {
            rmax0 = fmaxf(rmax0, __shfl_xor_sync(0xffffffffu, rmax0, o));
            rmax1 = fmaxf(rmax1, __shfl_xor_sync(0xffffffffu, rmax1, o));
        }
        float nm0 = fmaxf(m0, rmax0), nm1 = fmaxf(m1, rmax1);
        float corr0 = __expf(m0 - nm0), corr1 = __expf(m1 - nm1);
        float rs0 = 0.f, rs1 = 0.f;
        #pragma unroll
        for (int nn = 0; nn < 8; nn++) {
            float p00 = __expf(sv[nn][0] - nm0);
            float p01 = __expf(sv[nn][1] - nm0);
            float p10 = __expf(sv[nn][2] - nm1);
            float p11 = __expf(sv[nn][3] - nm1);
            rs0 += p00 + p01; rs1 += p10 + p11;
            int c = nn * 8 + tig * 2;
            pw[g * PS_STRIDE + c]           = f2tf32(p00);
            pw[g * PS_STRIDE + c + 1]       = f2tf32(p01);
            pw[(g + 8) * PS_STRIDE + c]     = f2tf32(p10);
            pw[(g + 8) * PS_STRIDE + c + 1] = f2tf32(p11);
        }
        #pragma unroll
        for (int o = 1; o <= 2; o <<= 1) {
            rs0 += __shfl_xor_sync(0xffffffffu, rs0, o);
            rs1 += __shfl_xor_sync(0xffffffffu, rs1, o);
        }
        l0 = l0 * corr0 + rs0;  m0 = nm0;
        l1 = l1 * corr1 + rs1;  m1 = nm1;
        #pragma unroll
        for (int nn = 0; nn < 12; nn++) {
            o_acc[nn][0] *= corr0; o_acc[nn][1] *= corr0;
            o_acc[nn][2] *= corr1; o_acc[nn][3] *= corr1;
        }
        __syncwarp();

        #pragma unroll
        for (int kk = 0; kk < 8; kk++) {
            uint32_t a[4];
            a[0] = pw[g * PS_STRIDE + kk * 8 + tig];
            a[1] = pw[(g + 8) * PS_STRIDE + kk * 8 + tig];
            a[2] = pw[g * PS_STRIDE + kk * 8 + tig + 4];
            a[3] = pw[(g + 8) * PS_STRIDE + kk * 8 + tig + 4];
            #pragma unroll
            for (int nn = 0; nn < 12; nn++) {
                uint32_t bb[2];
                bb[0] = vsb[(kk * 8 + tig) * VS_STRIDE + nn * 8 + g];
                bb[1] = vsb[(kk * 8 + tig + 4) * VS_STRIDE + nn * 8 + g];
                mma_tf32(o_acc[nn], a, bb);
            }
        }
        __syncwarp();
    }

    float inv0 = 1.f / l0, inv1 = 1.f / l1;
    int tok0 = b * N_ + i0 + row_a0;
    int tok1 = b * N_ + i0 + row_a1;
    int a0 = tok0 * H_ + h, a1 = tok1 * H_ + h;
    float ga0 = g_gate[a0], ga1 = g_gate[a1];
    #pragma unroll
    for (int nn = 0; nn < 12; nn++) {
        int c = nn * 8 + tig * 2;
        g_ot[(size_t)a0 * HD_ + c]     = f2tf32(ga0 * (o_acc[nn][0] * inv0));
        g_ot[(size_t)a0 * HD_ + c + 1] = f2tf32(ga0 * (o_acc[nn][1] * inv0));
        g_ot[(size_t)a1 * HD_ + c]     = f2tf32(ga1 * (o_acc[nn][2] * inv1));
        g_ot[(size_t)a1 * HD_ + c + 1] = f2tf32(ga1 * (o_acc[nn][3] * inv1));
    }
}

/* -- grouped reduce: 128-assignment tiles, cp.async dbuf, v2-red epilogue ---- */
/* osT [128][100] single fill; w2T 2 x 48-col chunks (16 chunks over 768)      */
#define RED_SMEM_WORDS (128*100 + 2*48*100)   /* 89600 bytes */
__global__ void __launch_bounds__(256) red_tc_kernel(float* __restrict__ out) {
    int e = blockIdx.y;
    int count = g_ecount[e];
    int base = blockIdx.x * 128;
    if (base >= count) return;

    extern __shared__ uint32_t rsm[];
    uint32_t* osT = rsm;                      /* [128][100]   */
    uint32_t* w2T = rsm + 128 * 100;          /* [2][48][100] */
    __shared__ int s_a[128];

    int tid = threadIdx.x;
    if (tid < 128) {
        int idx = base + tid; if (idx >= count) idx = count - 1;
        s_a[tid] = g_elist[e * NA + idx];
    }
    __syncthreads();

    uint32_t osT_s = (uint32_t)__cvta_generic_to_shared(osT);
    uint32_t w2T_s = (uint32_t)__cvta_generic_to_shared(w2T);
    const uint32_t* w2te = g_w2t + (size_t)e * DIM_ * HD_;

    /* osT fill: 128 rows x 24 segs = 3072 ops (gathered) */
    #pragma unroll
    for (int j = 0; j < 12; j++) {
        int item = tid + 256 * j;
        int r = item / 24, seg = item % 24;
        int a = s_a[r];
        cp_async16(osT_s + (r * 100 + seg * 4) * 4,
                   g_ot + (size_t)a * HD_ + seg * 4);
    }

    auto fill_w2 = [&](int bi, int ct) {
        uint32_t wb = w2T_s + bi * (48 * 100 * 4);
        const uint32_t* src = w2te + (size_t)(ct * 48) * HD_;
        #pragma unroll
        for (int j = 0; j < 5; j++) {              /* 48 x 24 = 1152 ops */
            int item = tid + 256 * j;
            if (item < 1152) {
                int c = item / 24, seg = item % 24;
                cp_async16(wb + (c * 100 + seg * 4) * 4,
                           src + (size_t)c * HD_ + seg * 4);
            }
        }
        cp_commit();   /* first call also commits the osT ops above */
    };
    fill_w2(0, 0);

    int wid = tid >> 5, lane = tid & 31;
    int g = lane >> 2, tig = lane & 3;
    int row_a0 = wid * 16 + g, row_a1 = row_a0 + 8;
    bool ok0 = (base + row_a0 < count), ok1 = (base + row_a1 < count);
    int t0 = s_a[row_a0] >> 3, t1 = s_a[row_a1] >> 3;

    for (int ct = 0; ct < 16; ct++) {
        if (ct < 15) fill_w2((ct + 1) & 1, ct + 1);
        if (ct < 15) cp_wait<1>(); else cp_wait<0>();
        __syncthreads();
        uint32_t* wsb = w2T + (ct & 1) * 48 * 100;

        float acc[6][4];
        #pragma unroll
        for (int nn = 0; nn < 6; nn++)
            #pragma unroll
            for (int r = 0; r < 4; r++) acc[nn][r] = 0.f;

        #pragma unroll
        for (int kk = 0; kk < 12; kk++) {
            uint32_t a[4];
            a[0] = osT[row_a0 * 100 + kk * 8 + tig];
            a[1] = osT[row_a1 * 100 + kk * 8 + tig];
            a[2] = osT[row_a0 * 100 + kk * 8 + tig + 4];
            a[3] = osT[row_a1 * 100 + kk * 8 + tig + 4];
            #pragma unroll
            for (int nn = 0; nn < 6; nn++) {
                uint32_t bb[2];
                bb[0] = wsb[(nn * 8 + g) * 100 + kk * 8 + tig];
                bb[1] = wsb[(nn * 8 + g) * 100 + kk * 8 + tig + 4];
                mma_tf32(acc[nn], a, bb);
            }
        }

        #pragma unroll
        for (int nn = 0; nn < 6; nn++) {
            int c = ct * 48 + nn * 8 + tig * 2;
            if (ok0) red_add_v2(&out[(size_t)t0 * DIM_ + c], acc[nn][0], acc[nn][1]);
            if (ok1) red_add_v2(&out[(size_t)t1 * DIM_ + c], acc[nn][2], acc[nn][3]);
        }
        __syncthreads();
    }
}

/* ------------- aux loss + restore zeroed gating state for next run ---------- */
__global__ void aux_kernel(float* __restrict__ out, int out_size) {
    int tid = threadIdx.x;
    if (tid == 0) {
        float mesum = 0.f;
        for (int e = 0; e < E_; e++) mesum += g_me[e];
        float sw = 0.f;
        for (int e = 0; e < E_; e++)
            sw += (g_me[e] / mesum) * ((float)g_ecount[e] / (float)NA);
        sw *= (float)E_;
        float z = g_z / (float)NT;
        float aux = 0.1f * sw + 0.001f * z;
        if (out_size > NT * DIM_) out[out_size - 1] = aux;
    }
    __syncwarp();
    if (tid < E_) { g_me[tid] = 0.f; g_ecount[tid] = 0; }
    if (tid == 0) g_z = 0.f;
}

/* -------------------------------- launch ------------------------------------ */
extern "C" void kernel_launch(void* const* d_in, const int* in_sizes, int n_in,
                              void* d_out, int out_size) {
    const float* x    = (const float*)d_in[0];
    const float* Wg   = (const float*)d_in[1];
    const float* W1   = (const float*)d_in[2];
    const float* W2   = (const float*)d_in[3];
    const float* Wkv  = (const float*)d_in[4];
    const float* bkv  = (const float*)d_in[5];
    const int*   task = (const int*)d_in[6];
    float* out = (float*)d_out;

    cudaFuncSetAttribute(attn_tc_kernel,
                         cudaFuncAttributeMaxDynamicSharedMemorySize,
                         ATTN_SMEM_WORDS * (int)sizeof(uint32_t));
    cudaFuncSetAttribute(red_tc_kernel,
                         cudaFuncAttributeMaxDynamicSharedMemorySize,
                         RED_SMEM_WORDS * (int)sizeof(uint32_t));
    cudaFuncSetAttribute(q_tc_kernel,
                         cudaFuncAttributeMaxDynamicSharedMemorySize,
                         Q_SMEM_WORDS * (int)sizeof(uint32_t));

    prep_kernel<<<1536, 256>>>(x, Wg, W1, W2, Wkv, bkv, task, out, out_size); /* #1 */
    q_tc_kernel<<<dim3(64, E_), 256, Q_SMEM_WORDS * sizeof(uint32_t)>>>();   /* #2 */
    attn_tc_kernel<<<dim3(8, B_ * H_), 256,
                     ATTN_SMEM_WORDS * sizeof(uint32_t)>>>();                /* #3 */
    red_tc_kernel<<<dim3(64, E_), 256,
                    RED_SMEM_WORDS * sizeof(uint32_t)>>>(out);               /* #4 */
    aux_kernel<<<1, 32>>>(out, out_size);                                    /* #5 */
}